// round 8
// baseline (speedup 1.0000x reference)
#include <cuda_runtime.h>
#include <cuda_bf16.h>
#include <cstdint>

#define N_SAMP   262144
#define ZD       2
#define CTX      128
#define HID      128
#define TEMB     32
#define NSTEPS   50
#define SPB      64      // samples per block
#define NTHREADS 512     // 16 warps: per MLP 8 warps = 4 sample-groups x 2 N-halves

// output layout: traj [51,N,2] | us [50,N,2] | times [51]
#define US_OFF    ((long long)(NSTEPS+1) * N_SAMP * ZD)
#define TAIL_OFF  (US_OFF + (long long)NSTEPS * N_SAMP * ZD)

// per-step constants, tw permuted into per-lane fragment order:
// idx = i*128 + kt*16 + t*4 + comp,  comp = reg*2 + half  (k = kt*16 + 2t + reg*8 + half)
__device__ float g_twd[NSTEPS * HID];
__device__ float g_twc[NSTEPS * HID];
__device__ float g_dts[NSTEPS];
__device__ float g_coef[NSTEPS];

// fast silu: x*sigmoid(x) = 0.5x + 0.5x*tanh(0.5x)  (1 MUFU.TANH)
__device__ __forceinline__ float fsilu(float x) {
    float h = 0.5f * x;
    float t;
    asm("tanh.approx.f32 %0, %1;" : "=f"(t) : "f"(h));
    return fmaf(h, t, h);
}
// pack: lower half = even-k val, upper half = odd-k val
__device__ __forceinline__ uint32_t cvt2bf(float odd_k, float even_k) {
    uint32_t r; asm("cvt.rn.bf16x2.f32 %0, %1, %2;" : "=r"(r) : "f"(odd_k), "f"(even_k)); return r;
}
__device__ __forceinline__ void mma16816(float* d, uint32_t a0, uint32_t a1,
                                         uint32_t a2, uint32_t a3,
                                         uint32_t b0, uint32_t b1) {
    asm volatile("mma.sync.aligned.m16n8k16.row.col.f32.bf16.bf16.f32 "
                 "{%0,%1,%2,%3}, {%4,%5,%6,%7}, {%8,%9}, {%0,%1,%2,%3};"
                 : "+f"(d[0]), "+f"(d[1]), "+f"(d[2]), "+f"(d[3])
                 : "r"(a0), "r"(a1), "r"(a2), "r"(a3), "r"(b0), "r"(b1));
}

// fragment position helpers (k within 128): kt = k>>4, kr = k&15
// t = (kr&7)>>1, reg = (kr>>3)&1, half = kr&1, comp = reg*2 + half
__host__ __device__ __forceinline__ int frag_comp(int kr) { return (((kr >> 3) & 1) << 1) | (kr & 1); }

// ---------------------------------------------------------------------------
// Kernel A: per-step constants (temb @ W1_temb + b1 in permuted layout) + times tail
// ---------------------------------------------------------------------------
__global__ void prep_kernel(const float* __restrict__ times,
                            const float* __restrict__ freqs,
                            const float* __restrict__ dW1, const float* __restrict__ db1,
                            const float* __restrict__ cW1, const float* __restrict__ cb1,
                            const float* __restrict__ log_diff,
                            float* __restrict__ out)
{
    __shared__ float temb[TEMB];
    int tid = threadIdx.x;  // 128 threads, tid = k
    if (tid < NSTEPS + 1) out[TAIL_OFF + tid] = times[tid];
    int kt = tid >> 4, kr = tid & 15;
    int pidx = kt * 16 + ((kr & 7) >> 1) * 4 + frag_comp(kr);  // permuted position
    float gb = log1pf(__expf(log_diff[0]));  // softplus
    for (int i = 0; i < NSTEPS; i++) {
        float t = times[i];
        __syncthreads();
        if (tid < TEMB / 2) {
            float a = 6.2831853071795864f * t * freqs[tid];
            temb[tid]            = sinf(a);
            temb[tid + TEMB / 2] = cosf(a);
        }
        __syncthreads();
        float ad = db1[tid], ac = cb1[tid];
#pragma unroll 8
        for (int mm = 0; mm < TEMB; mm++) {
            float tv = temb[mm];
            ad += tv * dW1[(ZD + CTX + mm) * HID + tid];
            ac += tv * cW1[(ZD + CTX + mm) * HID + tid];
        }
        g_twd[i * HID + pidx] = ad;
        g_twc[i * HID + pidx] = ac;
        if (tid == 0) {
            float dt = times[i + 1] - t;
            g_dts[i]  = dt;
            g_coef[i] = gb * (1.0f - t) * sqrtf(fmaxf(dt, 1e-12f));
        }
    }
}

// ---------------------------------------------------------------------------
// base = ctx @ W1[2:130] for one group of 8 samples (old [s][k] layout)
// ---------------------------------------------------------------------------
__device__ __forceinline__ void compute_base(float* __restrict__ dst,
                                             const float* __restrict__ tmp,
                                             const float* __restrict__ W1,
                                             int grp, int l)
{
    float acc[8][4];
#pragma unroll
    for (int s8 = 0; s8 < 8; s8++)
#pragma unroll
        for (int c = 0; c < 4; c++) acc[s8][c] = 0.f;
#pragma unroll 2
    for (int r = 0; r < CTX; r++) {
        float w1v[4];
#pragma unroll
        for (int c = 0; c < 4; c++) w1v[c] = W1[(ZD + r) * HID + l + 32 * c];
#pragma unroll
        for (int s8 = 0; s8 < 8; s8++) {
            float a = tmp[(grp * 8 + s8) * HID + r];
#pragma unroll
            for (int c = 0; c < 4; c++) acc[s8][c] += a * w1v[c];
        }
    }
#pragma unroll
    for (int s8 = 0; s8 < 8; s8++)
#pragma unroll
        for (int c = 0; c < 4; c++)
            dst[(grp * 8 + s8) * HID + l + 32 * c] = acc[s8][c];
}

// ---------------------------------------------------------------------------
// Kernel B: persistent 50-step SDE, tensor-core layer-2, 16 samples/warp,
// N-dim split across warp pairs for tensor-pipe overlap.
// 512 threads: warps 0-7 diffusion MLP, 8-15 cnf MLP.
// Within an MLP: wg = (w>>1)&3 picks 16 samples, nh = w&1 picks N half (64 cols).
// SMEM: BfD(64K) BfC(64K) baseRD(32K) baseRC(32K) + tables + psum ≈ 205KB.
// ---------------------------------------------------------------------------
__global__ void __launch_bounds__(NTHREADS, 1)
sde_kernel(const float* __restrict__ z0,
           const float* __restrict__ pctx, const float* __restrict__ cctx,
           const float* __restrict__ noise,
           const float* __restrict__ dW1, const float* __restrict__ dW2,
           const float* __restrict__ db2, const float* __restrict__ dW3,
           const float* __restrict__ db3,
           const float* __restrict__ cW1, const float* __restrict__ cW2,
           const float* __restrict__ cb2, const float* __restrict__ cW3,
           const float* __restrict__ cb3,
           float* __restrict__ out)
{
    extern __shared__ float sm[];
    uint4* BfD    = (uint4*)sm;              // 8kt*16ntg*32lane uint4 = 64KB
    uint4* BfC    = BfD + 4096;              // 64KB
    float* baseRD = (float*)(BfC + 4096);    // 4 wg * 2048 floats = 32KB
    float* baseRC = baseRD + 8192;           // 32KB
    float* wzRs   = baseRC + 8192;           // [mlp][row][kt][t] float4 = 512 f
    float* b2Rs   = wzRs + 512;              // [mlp][ntg][t] float2 = 256 f
    float* W3Rs   = b2Rs + 256;              // [mlp][ntg][t] float4 = 512 f
    float2* psum2 = (float2*)(W3Rs + 512);   // [2 buf][2 mlp][2 nh][64] float2 = 8KB

    int tid = threadIdx.x;
    int w = tid >> 5, l = tid & 31;
    int m   = w >> 3;        // 0 = diffusion (u), 1 = cnf (f)
    int sub = w & 7;
    int wg  = sub >> 1;      // sample group of 16
    int nh  = sub & 1;       // N half: columns [nh*64, nh*64+64)
    int t3 = l & 3;          // quad thread
    int g  = l >> 2;         // row 0-7 (sample A); sample B = row g+8
    int blockBase = blockIdx.x * SPB;
    int sA = wg * 16 + g;    // sample index within CTA
    int sB = sA + 8;
    int gsA = blockBase + sA;
    int gsB = blockBase + sB;

    // ================= phase 1 =================
    // 1) stage ctx tiles into the (not yet used) Bfrag regions
    {
        float* tD = (float*)BfD;
        float* tC = (float*)BfC;
        for (int idx = tid; idx < SPB * HID; idx += NTHREADS) {
            tD[idx] = pctx[(long long)blockBase * HID + idx];
            tC[idx] = cctx[(long long)blockBase * HID + idx];
        }
    }
    __syncthreads();
    // 2) base in old [s][k] layout: each warp computes one group of 8 samples
    if (m == 0) compute_base(baseRD, (float*)BfD, dW1, sub, l);
    else        compute_base(baseRC, (float*)BfC, cW1, sub, l);
    __syncthreads();
    // 3) in-place permute base -> fragment order:
    //    ni = ((swg*8 + kt)*32 + lane)*8 + hi8*4 + comp
    {
        float tmpv[16];
#pragma unroll
        for (int a = 0; a < 2; a++) {
            float* arr = a ? baseRC : baseRD;
#pragma unroll
            for (int q = 0; q < 16; q++) tmpv[q] = arr[tid * 16 + q];
            __syncthreads();
#pragma unroll
            for (int q = 0; q < 16; q++) {
                int idx = tid * 16 + q;
                int s = idx >> 7, k = idx & 127;
                int swg = s >> 4, srow = s & 15;
                int hi8 = srow >> 3, gg = srow & 7;
                int kt = k >> 4, kr = k & 15;
                int lane = gg * 4 + ((kr & 7) >> 1);
                int ni = ((swg * 8 + kt) * 32 + lane) * 8 + hi8 * 4 + frag_comp(kr);
                arr[ni] = tmpv[q];
            }
            __syncthreads();
        }
    }
    // 4) W2 -> bf16 hi/lo in B-fragment layout; plus small tables
    {
        unsigned short* bD16 = (unsigned short*)BfD;
        unsigned short* bC16 = (unsigned short*)BfC;
        for (int e = tid; e < HID * HID; e += NTHREADS) {
            int k = e >> 7, j = e & 127;
            int kt = k >> 4, kr = k & 15;
            int reg = (kr >> 3) & 1, half = kr & 1;
            int lane = (j & 7) * 4 + ((kr & 7) >> 1);
            int ntg = j >> 3;
            int slot = (((kt * 16 + ntg) * 32 + lane) * 4);
            {
                float wv = dW2[e];
                __nv_bfloat16 hb = __float2bfloat16(wv);
                __nv_bfloat16 lb = __float2bfloat16(wv - __bfloat162float(hb));
                bD16[(slot + reg) * 2 + half]     = __bfloat16_as_ushort(hb);
                bD16[(slot + 2 + reg) * 2 + half] = __bfloat16_as_ushort(lb);
            }
            {
                float wv = cW2[e];
                __nv_bfloat16 hb = __float2bfloat16(wv);
                __nv_bfloat16 lb = __float2bfloat16(wv - __bfloat162float(hb));
                bC16[(slot + reg) * 2 + half]     = __bfloat16_as_ushort(hb);
                bC16[(slot + 2 + reg) * 2 + half] = __bfloat16_as_ushort(lb);
            }
        }
        // wzR: [mlp][row][kt][t][comp]
        for (int idx = tid; idx < 2 * 2 * HID; idx += NTHREADS) {
            int mlp = idx >> 8, row = (idx >> 7) & 1, k = idx & 127;
            int kt = k >> 4, kr = k & 15;
            float v = (mlp ? cW1 : dW1)[row * HID + k];
            wzRs[((mlp * 2 + row) * 8 + kt) * 16 + ((kr & 7) >> 1) * 4 + frag_comp(kr)] = v;
        }
        // b2R: [mlp][ntg][t][half]   (j = ntg*8 + 2t + half)
        for (int idx = tid; idx < 2 * HID; idx += NTHREADS) {
            int mlp = idx >> 7, j = idx & 127;
            float v = (mlp ? cb2 : db2)[j];
            b2Rs[(mlp * 16 + (j >> 3)) * 8 + ((j & 7) >> 1) * 2 + (j & 1)] = v;
        }
        // W3R: [mlp][ntg][t][(j&1)*2 + d]
        for (int idx = tid; idx < 2 * HID * ZD; idx += NTHREADS) {
            int mlp = idx >> 8, j = (idx >> 1) & 127, d = idx & 1;
            float v = (mlp ? cW3 : dW3)[j * ZD + d];
            W3Rs[(mlp * 16 + (j >> 3)) * 16 + ((j & 7) >> 1) * 4 + (j & 1) * 2 + d] = v;
        }
    }
    __syncthreads();

    // ================= per-warp constant pointers / regs =================
    const uint4*  Bf    = m ? BfC : BfD;
    const float4* bR4   = (const float4*)(m ? baseRC : baseRD);
    const float4* twR4  = (const float4*)(m ? g_twc : g_twd);
    const float4* wz04  = (const float4*)wzRs + (m * 2 + 0) * 32;
    const float4* wz14  = (const float4*)wzRs + (m * 2 + 1) * 32;
    const float2* b2R2  = (const float2*)b2Rs + m * 64;
    const float4* W3R4  = (const float4*)W3Rs + m * 64;
    const float2* noise2 = (const float2*)noise;
    float2* outTraj = (float2*)out;
    float2* outUS   = (float2*)(out + US_OFF);

    // both MLPs' b3 (own added to partial after halves-sum; other's for z update)
    float b3m0 = (m ? cb3 : db3)[0], b3m1 = (m ? cb3 : db3)[1];
    float b3o0 = (m ? db3 : cb3)[0], b3o1 = (m ? db3 : cb3)[1];

    // init z (all 4 lanes of quad hold both samples' z)
    float2 ziA = __ldg(&((const float2*)z0)[gsA]);
    float2 ziB = __ldg(&((const float2*)z0)[gsB]);
    float zA0 = ziA.x, zA1 = ziA.y, zB0 = ziB.x, zB1 = ziB.y;
    if (m == 1 && nh == 0 && t3 == 0) { outTraj[gsA] = ziA; outTraj[gsB] = ziB; }

    // ================= 50-step loop =================
    for (int i = 0; i < NSTEPS; i++) {
        float dt = g_dts[i], cf = g_coef[i];
        long long io = (long long)i * N_SAMP;
        float2 xiA = __ldg(&noise2[io + gsA]);
        float2 xiB = __ldg(&noise2[io + gsB]);

        float d[8][4];
#pragma unroll
        for (int nt = 0; nt < 8; nt++)
#pragma unroll
            for (int c = 0; c < 4; c++) d[nt][c] = 0.f;

        // ---- fused layer-1 (A frags in regs) + tensor layer-2 over my N half ----
#pragma unroll
        for (int kt = 0; kt < 8; kt++) {
            float4 bsA = bR4[((wg * 8 + kt) * 32 + l) * 2 + 0];
            float4 bsB = bR4[((wg * 8 + kt) * 32 + l) * 2 + 1];
            float4 tw  = __ldg(&twR4[i * 32 + kt * 4 + t3]);
            float4 w0  = wz04[kt * 4 + t3];
            float4 w1  = wz14[kt * 4 + t3];
            float hAx = fsilu(bsA.x + tw.x + zA0 * w0.x + zA1 * w1.x);
            float hAy = fsilu(bsA.y + tw.y + zA0 * w0.y + zA1 * w1.y);
            float hAz = fsilu(bsA.z + tw.z + zA0 * w0.z + zA1 * w1.z);
            float hAw = fsilu(bsA.w + tw.w + zA0 * w0.w + zA1 * w1.w);
            float hBx = fsilu(bsB.x + tw.x + zB0 * w0.x + zB1 * w1.x);
            float hBy = fsilu(bsB.y + tw.y + zB0 * w0.y + zB1 * w1.y);
            float hBz = fsilu(bsB.z + tw.z + zB0 * w0.z + zB1 * w1.z);
            float hBw = fsilu(bsB.w + tw.w + zB0 * w0.w + zB1 * w1.w);
            uint32_t a0h = cvt2bf(hAy, hAx);
            uint32_t a1h = cvt2bf(hBy, hBx);
            uint32_t a2h = cvt2bf(hAw, hAz);
            uint32_t a3h = cvt2bf(hBw, hBz);
            uint32_t a0l = cvt2bf(hAy - __uint_as_float(a0h & 0xffff0000u),
                                  hAx - __uint_as_float(a0h << 16));
            uint32_t a1l = cvt2bf(hBy - __uint_as_float(a1h & 0xffff0000u),
                                  hBx - __uint_as_float(a1h << 16));
            uint32_t a2l = cvt2bf(hAw - __uint_as_float(a2h & 0xffff0000u),
                                  hAz - __uint_as_float(a2h << 16));
            uint32_t a3l = cvt2bf(hBw - __uint_as_float(a3h & 0xffff0000u),
                                  hBz - __uint_as_float(a3h << 16));
#pragma unroll
            for (int ntc = 0; ntc < 8; ntc += 4) {
                uint4 Bv[4];
#pragma unroll
                for (int q = 0; q < 4; q++)
                    Bv[q] = Bf[(kt * 16 + nh * 8 + ntc + q) * 32 + l];
#pragma unroll
                for (int q = 0; q < 4; q++)
                    mma16816(d[ntc + q], a0h, a1h, a2h, a3h, Bv[q].x, Bv[q].y);
#pragma unroll
                for (int q = 0; q < 4; q++)
                    mma16816(d[ntc + q], a0l, a1l, a2l, a3l, Bv[q].x, Bv[q].y);
#pragma unroll
                for (int q = 0; q < 4; q++)
                    mma16816(d[ntc + q], a0h, a1h, a2h, a3h, Bv[q].z, Bv[q].w);
            }
        }

        // ---- epilogue: silu(h2+b2), layer-3 partials over my N half ----
        float aA0 = 0.f, aA1 = 0.f, aB0 = 0.f, aB1 = 0.f;
#pragma unroll
        for (int nt = 0; nt < 8; nt++) {
            int ntg = nh * 8 + nt;
            float2 b2v = b2R2[ntg * 4 + t3];
            float4 w3v = W3R4[ntg * 4 + t3];
            float x0 = fsilu(d[nt][0] + b2v.x);
            float x1 = fsilu(d[nt][1] + b2v.y);
            float x2 = fsilu(d[nt][2] + b2v.x);
            float x3 = fsilu(d[nt][3] + b2v.y);
            aA0 += x0 * w3v.x + x1 * w3v.z;
            aA1 += x0 * w3v.y + x1 * w3v.w;
            aB0 += x2 * w3v.x + x3 * w3v.z;
            aB1 += x2 * w3v.y + x3 * w3v.w;
        }

        // ---- quad reduction (all lanes get sums) ----
        aA0 += __shfl_xor_sync(0xffffffffu, aA0, 1);
        aA1 += __shfl_xor_sync(0xffffffffu, aA1, 1);
        aB0 += __shfl_xor_sync(0xffffffffu, aB0, 1);
        aB1 += __shfl_xor_sync(0xffffffffu, aB1, 1);
        aA0 += __shfl_xor_sync(0xffffffffu, aA0, 2);
        aA1 += __shfl_xor_sync(0xffffffffu, aA1, 2);
        aB0 += __shfl_xor_sync(0xffffffffu, aB0, 2);
        aB1 += __shfl_xor_sync(0xffffffffu, aB1, 2);

        // ---- partial-sum exchange: [buf][mlp][nh][64] (one barrier per step) ----
        int bufo = (i & 1) * 256;
        if (t3 == 0) {
            psum2[bufo + m * 128 + nh * 64 + sA] = make_float2(aA0, aA1);
            psum2[bufo + m * 128 + nh * 64 + sB] = make_float2(aB0, aB1);
        }
        __syncthreads();

        float2 mA0 = psum2[bufo + m * 128 +       sA];
        float2 mA1 = psum2[bufo + m * 128 + 64 +  sA];
        float2 mB0 = psum2[bufo + m * 128 +       sB];
        float2 mB1 = psum2[bufo + m * 128 + 64 +  sB];
        float2 oA0 = psum2[bufo + (1 - m) * 128 +      sA];
        float2 oA1 = psum2[bufo + (1 - m) * 128 + 64 + sA];
        float2 oB0 = psum2[bufo + (1 - m) * 128 +      sB];
        float2 oB1 = psum2[bufo + (1 - m) * 128 + 64 + sB];

        float vA0 = mA0.x + mA1.x + b3m0, vA1 = mA0.y + mA1.y + b3m1;
        float vB0 = mB0.x + mB1.x + b3m0, vB1 = mB0.y + mB1.y + b3m1;
        float uA0 = oA0.x + oA1.x + b3o0, uA1 = oA0.y + oA1.y + b3o1;
        float uB0 = oB0.x + oB1.x + b3o0, uB1 = oB0.y + oB1.y + b3o1;

        zA0 += (vA0 + uA0) * dt + xiA.x * cf;
        zA1 += (vA1 + uA1) * dt + xiA.y * cf;
        zB0 += (vB0 + uB0) * dt + xiB.x * cf;
        zB1 += (vB1 + uB1) * dt + xiB.y * cf;

        if (nh == 0 && t3 == 0) {
            if (m == 0) {
                outUS[io + gsA] = make_float2(vA0, vA1);
                outUS[io + gsB] = make_float2(vB0, vB1);
            } else {
                outTraj[(long long)(i + 1) * N_SAMP + gsA] = make_float2(zA0, zA1);
                outTraj[(long long)(i + 1) * N_SAMP + gsB] = make_float2(zB0, zB1);
            }
        }
    }
}

// ---------------------------------------------------------------------------
extern "C" void kernel_launch(void* const* d_in, const int* in_sizes, int n_in,
                              void* d_out, int out_size)
{
    const float* z0       = (const float*)d_in[0];
    const float* pctx     = (const float*)d_in[1];
    const float* cctx     = (const float*)d_in[2];
    const float* times    = (const float*)d_in[3];
    const float* noise    = (const float*)d_in[4];
    const float* freqs    = (const float*)d_in[5];
    const float* dW1      = (const float*)d_in[6];
    const float* db1      = (const float*)d_in[7];
    const float* dW2      = (const float*)d_in[8];
    const float* db2      = (const float*)d_in[9];
    const float* dW3      = (const float*)d_in[10];
    const float* db3      = (const float*)d_in[11];
    const float* cW1      = (const float*)d_in[12];
    const float* cb1      = (const float*)d_in[13];
    const float* cW2      = (const float*)d_in[14];
    const float* cb2      = (const float*)d_in[15];
    const float* cW3      = (const float*)d_in[16];
    const float* cb3      = (const float*)d_in[17];
    const float* log_diff = (const float*)d_in[18];
    float* out = (float*)d_out;

    // Bf 2*64KB + baseR 2*32KB + wzR 2KB + b2R 1KB + W3R 2KB + psum 8KB
    const int smemB = 2 * 65536 + 2 * 32768 + 512 * 4 + 256 * 4 + 512 * 4 + 1024 * 8;
    cudaFuncSetAttribute(sde_kernel, cudaFuncAttributeMaxDynamicSharedMemorySize, smemB);

    prep_kernel<<<1, 128>>>(times, freqs, dW1, db1, cW1, cb1, log_diff, out);
    sde_kernel<<<N_SAMP / SPB, NTHREADS, smemB>>>(z0, pctx, cctx, noise,
                                                  dW1, dW2, db2, dW3, db3,
                                                  cW1, cW2, cb2, cW3, cb3, out);
}

// round 9
// speedup vs baseline: 1.1271x; 1.1271x over previous
#include <cuda_runtime.h>
#include <cuda_bf16.h>
#include <cstdint>

#define N_SAMP   262144
#define ZD       2
#define CTX      128
#define HID      128
#define TEMB     32
#define NSTEPS   50
#define SPB      64      // samples per block
#define NTHREADS 256     // 8 warps: 4 diffusion + 4 cnf, 16 samples each

// output layout: traj [51,N,2] | us [50,N,2] | times [51]
#define US_OFF    ((long long)(NSTEPS+1) * N_SAMP * ZD)
#define TAIL_OFF  (US_OFF + (long long)NSTEPS * N_SAMP * ZD)

// per-step constants, tw permuted into per-lane fragment order:
// idx = i*128 + kt*16 + t*4 + comp,  comp = reg*2 + half  (k = kt*16 + 2t + reg*8 + half)
__device__ float g_twd[NSTEPS * HID];
__device__ float g_twc[NSTEPS * HID];
__device__ float g_dts[NSTEPS];
__device__ float g_coef[NSTEPS];

// fast silu: x*sigmoid(x) = 0.5x + 0.5x*tanh(0.5x)  (1 MUFU.TANH)
__device__ __forceinline__ float fsilu(float x) {
    float h = 0.5f * x;
    float t;
    asm("tanh.approx.f32 %0, %1;" : "=f"(t) : "f"(h));
    return fmaf(h, t, h);
}
// pack: lower half = even-k val, upper half = odd-k val
__device__ __forceinline__ uint32_t cvt2bf(float odd_k, float even_k) {
    uint32_t r; asm("cvt.rn.bf16x2.f32 %0, %1, %2;" : "=r"(r) : "f"(odd_k), "f"(even_k)); return r;
}
__device__ __forceinline__ void mma16816(float* d, uint32_t a0, uint32_t a1,
                                         uint32_t a2, uint32_t a3,
                                         uint32_t b0, uint32_t b1) {
    asm volatile("mma.sync.aligned.m16n8k16.row.col.f32.bf16.bf16.f32 "
                 "{%0,%1,%2,%3}, {%4,%5,%6,%7}, {%8,%9}, {%0,%1,%2,%3};"
                 : "+f"(d[0]), "+f"(d[1]), "+f"(d[2]), "+f"(d[3])
                 : "r"(a0), "r"(a1), "r"(a2), "r"(a3), "r"(b0), "r"(b1));
}
__device__ __forceinline__ void mbar_init(uint32_t addr, uint32_t cnt) {
    asm volatile("mbarrier.init.shared.b64 [%0], %1;" :: "r"(addr), "r"(cnt) : "memory");
}
__device__ __forceinline__ void mbar_arrive(uint32_t addr) {
    asm volatile("mbarrier.arrive.release.cta.shared::cta.b64 _, [%0];" :: "r"(addr) : "memory");
}
__device__ __forceinline__ void mbar_wait(uint32_t addr, uint32_t parity) {
    asm volatile("{\n\t"
                 ".reg .pred P1;\n\t"
                 "WAIT_%=:\n\t"
                 "mbarrier.try_wait.parity.acquire.cta.shared::cta.b64 P1, [%0], %1, 0x989680;\n\t"
                 "@P1 bra.uni DONE_%=;\n\t"
                 "bra.uni WAIT_%=;\n\t"
                 "DONE_%=:\n\t"
                 "}"
                 :: "r"(addr), "r"(parity) : "memory");
}

// fragment position helpers (k within 128): kt = k>>4, kr = k&15
// t = (kr&7)>>1, reg = (kr>>3)&1, half = kr&1, comp = reg*2 + half
__host__ __device__ __forceinline__ int frag_comp(int kr) { return (((kr >> 3) & 1) << 1) | (kr & 1); }

// ---------------------------------------------------------------------------
// Kernel A: per-step constants (temb @ W1_temb + b1 in permuted layout) + times tail
// ---------------------------------------------------------------------------
__global__ void prep_kernel(const float* __restrict__ times,
                            const float* __restrict__ freqs,
                            const float* __restrict__ dW1, const float* __restrict__ db1,
                            const float* __restrict__ cW1, const float* __restrict__ cb1,
                            const float* __restrict__ log_diff,
                            float* __restrict__ out)
{
    __shared__ float temb[TEMB];
    int tid = threadIdx.x;  // 128 threads, tid = k
    if (tid < NSTEPS + 1) out[TAIL_OFF + tid] = times[tid];
    int kt = tid >> 4, kr = tid & 15;
    int pidx = kt * 16 + ((kr & 7) >> 1) * 4 + frag_comp(kr);  // permuted position
    float gb = log1pf(__expf(log_diff[0]));  // softplus
    for (int i = 0; i < NSTEPS; i++) {
        float t = times[i];
        __syncthreads();
        if (tid < TEMB / 2) {
            float a = 6.2831853071795864f * t * freqs[tid];
            temb[tid]            = sinf(a);
            temb[tid + TEMB / 2] = cosf(a);
        }
        __syncthreads();
        float ad = db1[tid], ac = cb1[tid];
#pragma unroll 8
        for (int mm = 0; mm < TEMB; mm++) {
            float tv = temb[mm];
            ad += tv * dW1[(ZD + CTX + mm) * HID + tid];
            ac += tv * cW1[(ZD + CTX + mm) * HID + tid];
        }
        g_twd[i * HID + pidx] = ad;
        g_twc[i * HID + pidx] = ac;
        if (tid == 0) {
            float dt = times[i + 1] - t;
            g_dts[i]  = dt;
            g_coef[i] = gb * (1.0f - t) * sqrtf(fmaxf(dt, 1e-12f));
        }
    }
}

// ---------------------------------------------------------------------------
// base = ctx @ W1[2:130] for one group of 8 samples (old [s][k] layout)
// ---------------------------------------------------------------------------
__device__ __forceinline__ void compute_base(float* __restrict__ dst,
                                             const float* __restrict__ tmp,
                                             const float* __restrict__ W1,
                                             int grp, int l)
{
    float acc[8][4];
#pragma unroll
    for (int s8 = 0; s8 < 8; s8++)
#pragma unroll
        for (int c = 0; c < 4; c++) acc[s8][c] = 0.f;
#pragma unroll 2
    for (int r = 0; r < CTX; r++) {
        float w1v[4];
#pragma unroll
        for (int c = 0; c < 4; c++) w1v[c] = W1[(ZD + r) * HID + l + 32 * c];
#pragma unroll
        for (int s8 = 0; s8 < 8; s8++) {
            float a = tmp[(grp * 8 + s8) * HID + r];
#pragma unroll
            for (int c = 0; c < 4; c++) acc[s8][c] += a * w1v[c];
        }
    }
#pragma unroll
    for (int s8 = 0; s8 < 8; s8++)
#pragma unroll
        for (int c = 0; c < 4; c++)
            dst[(grp * 8 + s8) * HID + l + 32 * c] = acc[s8][c];
}

// ---------------------------------------------------------------------------
// Kernel B: persistent 50-step SDE, tensor-core layer-2, 16 samples/warp.
// 256 threads: warps 0-3 diffusion MLP, warps 4-7 cnf MLP, 16 samples/warp.
// Step sync: PAIRWISE mbarrier handshake between warp (0,wg) and (1,wg) —
// no CTA-wide barrier in the step loop, so warp pairs de-phase and the
// tensor pipe stays fed while other warps run SIMT phases.
// SMEM: BfD(64K) BfC(64K) baseRD(32K) baseRC(32K) + tables + psum + mbars ≈ 200KB.
// ---------------------------------------------------------------------------
__global__ void __launch_bounds__(NTHREADS, 1)
sde_kernel(const float* __restrict__ z0,
           const float* __restrict__ pctx, const float* __restrict__ cctx,
           const float* __restrict__ noise,
           const float* __restrict__ dW1, const float* __restrict__ dW2,
           const float* __restrict__ db2, const float* __restrict__ dW3,
           const float* __restrict__ db3,
           const float* __restrict__ cW1, const float* __restrict__ cW2,
           const float* __restrict__ cb2, const float* __restrict__ cW3,
           const float* __restrict__ cb3,
           float* __restrict__ out)
{
    extern __shared__ float sm[];
    uint4* BfD    = (uint4*)sm;              // 8kt*16ntg*32lane uint4 = 64KB
    uint4* BfC    = BfD + 4096;              // 64KB
    float* baseRD = (float*)(BfC + 4096);    // 4 wg * 2048 floats = 32KB
    float* baseRC = baseRD + 8192;           // 32KB
    float* wzRs   = baseRC + 8192;           // [mlp][row][kt][t] float4 = 512 f
    float* b2Rs   = wzRs + 512;              // [mlp][ntg][t] float2 = 256 f
    float* W3Rs   = b2Rs + 256;              // [mlp][ntg][t] float4 = 512 f
    float2* psum2 = (float2*)(W3Rs + 512);   // [2 buf][2 mlp][64] float2 = 2KB
    // mbarriers: [2 mlp][4 wg][2 buf] u64 = 128B  (after psum2: 256 float2)
    unsigned long long* mbars = (unsigned long long*)(psum2 + 256);

    int tid = threadIdx.x;
    int w = tid >> 5, l = tid & 31;
    int m  = w >> 2;       // 0 = diffusion (u), 1 = cnf (f)
    int wg = w & 3;        // sample group of 16
    int t3 = l & 3;        // quad thread
    int g  = l >> 2;       // row 0-7 (sample A); sample B = row g+8
    int blockBase = blockIdx.x * SPB;
    int sA = wg * 16 + g;
    int sB = sA + 8;
    int gsA = blockBase + sA;
    int gsB = blockBase + sB;

    // ================= phase 1 =================
    // 1) stage ctx tiles into the (not yet used) Bfrag regions
    {
        float* tD = (float*)BfD;
        float* tC = (float*)BfC;
        for (int idx = tid; idx < SPB * HID; idx += NTHREADS) {
            tD[idx] = pctx[(long long)blockBase * HID + idx];
            tC[idx] = cctx[(long long)blockBase * HID + idx];
        }
    }
    __syncthreads();
    // 2) base in old [s][k] layout: diffusion warps cover grp 0-7 for D, cnf for C
    if (m == 0) {
        compute_base(baseRD, (float*)BfD, dW1, wg * 2,     l);
        compute_base(baseRD, (float*)BfD, dW1, wg * 2 + 1, l);
    } else {
        compute_base(baseRC, (float*)BfC, cW1, wg * 2,     l);
        compute_base(baseRC, (float*)BfC, cW1, wg * 2 + 1, l);
    }
    __syncthreads();
    // 3) in-place permute base -> fragment order:
    //    ni = ((swg*8 + kt)*32 + lane)*8 + hi8*4 + comp
    {
        float tmpv[32];
#pragma unroll
        for (int a = 0; a < 2; a++) {
            float* arr = a ? baseRC : baseRD;
#pragma unroll
            for (int q = 0; q < 32; q++) tmpv[q] = arr[tid * 32 + q];
            __syncthreads();
#pragma unroll
            for (int q = 0; q < 32; q++) {
                int idx = tid * 32 + q;
                int s = idx >> 7, k = idx & 127;
                int swg = s >> 4, srow = s & 15;
                int hi8 = srow >> 3, gg = srow & 7;
                int kt = k >> 4, kr = k & 15;
                int lane = gg * 4 + ((kr & 7) >> 1);
                int ni = ((swg * 8 + kt) * 32 + lane) * 8 + hi8 * 4 + frag_comp(kr);
                arr[ni] = tmpv[q];
            }
            __syncthreads();
        }
    }
    // 4) W2 -> bf16 hi/lo in B-fragment layout; plus small tables; mbarrier init
    {
        unsigned short* bD16 = (unsigned short*)BfD;
        unsigned short* bC16 = (unsigned short*)BfC;
        for (int e = tid; e < HID * HID; e += NTHREADS) {
            int k = e >> 7, j = e & 127;
            int kt = k >> 4, kr = k & 15;
            int reg = (kr >> 3) & 1, half = kr & 1;
            int lane = (j & 7) * 4 + ((kr & 7) >> 1);
            int ntg = j >> 3;
            int slot = (((kt * 16 + ntg) * 32 + lane) * 4);
            {
                float wv = dW2[e];
                __nv_bfloat16 hb = __float2bfloat16(wv);
                __nv_bfloat16 lb = __float2bfloat16(wv - __bfloat162float(hb));
                bD16[(slot + reg) * 2 + half]     = __bfloat16_as_ushort(hb);
                bD16[(slot + 2 + reg) * 2 + half] = __bfloat16_as_ushort(lb);
            }
            {
                float wv = cW2[e];
                __nv_bfloat16 hb = __float2bfloat16(wv);
                __nv_bfloat16 lb = __float2bfloat16(wv - __bfloat162float(hb));
                bC16[(slot + reg) * 2 + half]     = __bfloat16_as_ushort(hb);
                bC16[(slot + 2 + reg) * 2 + half] = __bfloat16_as_ushort(lb);
            }
        }
        // wzR: [mlp][row][kt][t][comp]
        for (int idx = tid; idx < 2 * 2 * HID; idx += NTHREADS) {
            int mlp = idx >> 8, row = (idx >> 7) & 1, k = idx & 127;
            int kt = k >> 4, kr = k & 15;
            float v = (mlp ? cW1 : dW1)[row * HID + k];
            wzRs[((mlp * 2 + row) * 8 + kt) * 16 + ((kr & 7) >> 1) * 4 + frag_comp(kr)] = v;
        }
        // b2R: [mlp][ntg][t][half]   (j = ntg*8 + 2t + half)
        for (int idx = tid; idx < 2 * HID; idx += NTHREADS) {
            int mlp = idx >> 7, j = idx & 127;
            float v = (mlp ? cb2 : db2)[j];
            b2Rs[(mlp * 16 + (j >> 3)) * 8 + ((j & 7) >> 1) * 2 + (j & 1)] = v;
        }
        // W3R: [mlp][ntg][t][(j&1)*2 + d]
        for (int idx = tid; idx < 2 * HID * ZD; idx += NTHREADS) {
            int mlp = idx >> 8, j = (idx >> 1) & 127, d = idx & 1;
            float v = (mlp ? cW3 : dW3)[j * ZD + d];
            W3Rs[(mlp * 16 + (j >> 3)) * 16 + ((j & 7) >> 1) * 4 + (j & 1) * 2 + d] = v;
        }
        // 16 mbarriers, arrive count = 8 (the t3==0 lanes of one warp)
        if (tid < 16)
            mbar_init((uint32_t)__cvta_generic_to_shared(&mbars[tid]), 8);
    }
    __syncthreads();

    // ================= per-warp constant pointers / regs =================
    const uint4*  Bf    = m ? BfC : BfD;
    const float4* bR4   = (const float4*)(m ? baseRC : baseRD);
    const float4* twR4  = (const float4*)(m ? g_twc : g_twd);
    const float4* wz04  = (const float4*)wzRs + (m * 2 + 0) * 32;
    const float4* wz14  = (const float4*)wzRs + (m * 2 + 1) * 32;
    const float2* b2R2  = (const float2*)b2Rs + m * 64;
    const float4* W3R4  = (const float4*)W3Rs + m * 64;
    const float2* noise2 = (const float2*)noise;
    float2* outTraj = (float2*)out;
    float2* outUS   = (float2*)(out + US_OFF);

    // my mbar (arrive) and partner mbar (wait), per buffer
    uint32_t myBar0   = (uint32_t)__cvta_generic_to_shared(&mbars[(m * 4 + wg) * 2 + 0]);
    uint32_t myBar1   = (uint32_t)__cvta_generic_to_shared(&mbars[(m * 4 + wg) * 2 + 1]);
    uint32_t peerBar0 = (uint32_t)__cvta_generic_to_shared(&mbars[((1 - m) * 4 + wg) * 2 + 0]);
    uint32_t peerBar1 = (uint32_t)__cvta_generic_to_shared(&mbars[((1 - m) * 4 + wg) * 2 + 1]);

    float b3_0, b3_1;
    { const float* b3 = m ? cb3 : db3; b3_0 = b3[0]; b3_1 = b3[1]; }

    // init z (all 4 lanes of quad hold both samples' z)
    float2 ziA = __ldg(&((const float2*)z0)[gsA]);
    float2 ziB = __ldg(&((const float2*)z0)[gsB]);
    float zA0 = ziA.x, zA1 = ziA.y, zB0 = ziB.x, zB1 = ziB.y;
    if (m == 1 && t3 == 0) { outTraj[gsA] = ziA; outTraj[gsB] = ziB; }

    // ================= 50-step loop (no CTA barrier inside) =================
    for (int i = 0; i < NSTEPS; i++) {
        float dt = g_dts[i], cf = g_coef[i];
        long long io = (long long)i * N_SAMP;
        float2 xiA = __ldg(&noise2[io + gsA]);
        float2 xiB = __ldg(&noise2[io + gsB]);

        float d[16][4];
#pragma unroll
        for (int nt = 0; nt < 16; nt++)
#pragma unroll
            for (int c = 0; c < 4; c++) d[nt][c] = 0.f;

        // ---- fused layer-1 (A frags in regs) + tensor layer-2, per k-tile ----
#pragma unroll
        for (int kt = 0; kt < 8; kt++) {
            float4 bsA = bR4[((wg * 8 + kt) * 32 + l) * 2 + 0];
            float4 bsB = bR4[((wg * 8 + kt) * 32 + l) * 2 + 1];
            float4 tw  = __ldg(&twR4[i * 32 + kt * 4 + t3]);
            float4 w0  = wz04[kt * 4 + t3];
            float4 w1  = wz14[kt * 4 + t3];
            float hAx = fsilu(bsA.x + tw.x + zA0 * w0.x + zA1 * w1.x);
            float hAy = fsilu(bsA.y + tw.y + zA0 * w0.y + zA1 * w1.y);
            float hAz = fsilu(bsA.z + tw.z + zA0 * w0.z + zA1 * w1.z);
            float hAw = fsilu(bsA.w + tw.w + zA0 * w0.w + zA1 * w1.w);
            float hBx = fsilu(bsB.x + tw.x + zB0 * w0.x + zB1 * w1.x);
            float hBy = fsilu(bsB.y + tw.y + zB0 * w0.y + zB1 * w1.y);
            float hBz = fsilu(bsB.z + tw.z + zB0 * w0.z + zB1 * w1.z);
            float hBw = fsilu(bsB.w + tw.w + zB0 * w0.w + zB1 * w1.w);
            uint32_t a0h = cvt2bf(hAy, hAx);
            uint32_t a1h = cvt2bf(hBy, hBx);
            uint32_t a2h = cvt2bf(hAw, hAz);
            uint32_t a3h = cvt2bf(hBw, hBz);
            uint32_t a0l = cvt2bf(hAy - __uint_as_float(a0h & 0xffff0000u),
                                  hAx - __uint_as_float(a0h << 16));
            uint32_t a1l = cvt2bf(hBy - __uint_as_float(a1h & 0xffff0000u),
                                  hBx - __uint_as_float(a1h << 16));
            uint32_t a2l = cvt2bf(hAw - __uint_as_float(a2h & 0xffff0000u),
                                  hAz - __uint_as_float(a2h << 16));
            uint32_t a3l = cvt2bf(hBw - __uint_as_float(a3h & 0xffff0000u),
                                  hBz - __uint_as_float(a3h << 16));
#pragma unroll
            for (int ntc = 0; ntc < 16; ntc += 4) {
                uint4 Bv[4];
#pragma unroll
                for (int q = 0; q < 4; q++)
                    Bv[q] = Bf[(kt * 16 + ntc + q) * 32 + l];
#pragma unroll
                for (int q = 0; q < 4; q++)
                    mma16816(d[ntc + q], a0h, a1h, a2h, a3h, Bv[q].x, Bv[q].y);
#pragma unroll
                for (int q = 0; q < 4; q++)
                    mma16816(d[ntc + q], a0l, a1l, a2l, a3l, Bv[q].x, Bv[q].y);
#pragma unroll
                for (int q = 0; q < 4; q++)
                    mma16816(d[ntc + q], a0h, a1h, a2h, a3h, Bv[q].z, Bv[q].w);
            }
        }

        // ---- epilogue: silu(h2+b2), layer-3 partials (both samples) ----
        float aA0 = 0.f, aA1 = 0.f, aB0 = 0.f, aB1 = 0.f;
#pragma unroll
        for (int ntg = 0; ntg < 16; ntg++) {
            float2 b2v = b2R2[ntg * 4 + t3];
            float4 w3v = W3R4[ntg * 4 + t3];
            float x0 = fsilu(d[ntg][0] + b2v.x);
            float x1 = fsilu(d[ntg][1] + b2v.y);
            float x2 = fsilu(d[ntg][2] + b2v.x);
            float x3 = fsilu(d[ntg][3] + b2v.y);
            aA0 += x0 * w3v.x + x1 * w3v.z;
            aA1 += x0 * w3v.y + x1 * w3v.w;
            aB0 += x2 * w3v.x + x3 * w3v.z;
            aB1 += x2 * w3v.y + x3 * w3v.w;
        }

        // ---- quad reduction (all lanes get sums) ----
        aA0 += __shfl_xor_sync(0xffffffffu, aA0, 1);
        aA1 += __shfl_xor_sync(0xffffffffu, aA1, 1);
        aB0 += __shfl_xor_sync(0xffffffffu, aB0, 1);
        aB1 += __shfl_xor_sync(0xffffffffu, aB1, 1);
        aA0 += __shfl_xor_sync(0xffffffffu, aA0, 2);
        aA1 += __shfl_xor_sync(0xffffffffu, aA1, 2);
        aB0 += __shfl_xor_sync(0xffffffffu, aB0, 2);
        aB1 += __shfl_xor_sync(0xffffffffu, aB1, 2);
        float vA0 = aA0 + b3_0, vA1 = aA1 + b3_1;
        float vB0 = aB0 + b3_0, vB1 = aB1 + b3_1;

        // ---- pairwise mbarrier exchange (double-buffered) ----
        int buf = i & 1;
        uint32_t par = (i >> 1) & 1;
        int bufo = buf * 128;
        if (t3 == 0) {
            psum2[bufo + m * 64 + sA] = make_float2(vA0, vA1);
            psum2[bufo + m * 64 + sB] = make_float2(vB0, vB1);
            mbar_arrive(buf ? myBar1 : myBar0);
        }
        mbar_wait(buf ? peerBar1 : peerBar0, par);
        float2 ovA = psum2[bufo + (1 - m) * 64 + sA];
        float2 ovB = psum2[bufo + (1 - m) * 64 + sB];

        zA0 += (vA0 + ovA.x) * dt + xiA.x * cf;
        zA1 += (vA1 + ovA.y) * dt + xiA.y * cf;
        zB0 += (vB0 + ovB.x) * dt + xiB.x * cf;
        zB1 += (vB1 + ovB.y) * dt + xiB.y * cf;
        if (t3 == 0) {
            if (m == 0) {
                outUS[io + gsA] = make_float2(vA0, vA1);
                outUS[io + gsB] = make_float2(vB0, vB1);
            } else {
                outTraj[(long long)(i + 1) * N_SAMP + gsA] = make_float2(zA0, zA1);
                outTraj[(long long)(i + 1) * N_SAMP + gsB] = make_float2(zB0, zB1);
            }
        }
    }
}

// ---------------------------------------------------------------------------
extern "C" void kernel_launch(void* const* d_in, const int* in_sizes, int n_in,
                              void* d_out, int out_size)
{
    const float* z0       = (const float*)d_in[0];
    const float* pctx     = (const float*)d_in[1];
    const float* cctx     = (const float*)d_in[2];
    const float* times    = (const float*)d_in[3];
    const float* noise    = (const float*)d_in[4];
    const float* freqs    = (const float*)d_in[5];
    const float* dW1      = (const float*)d_in[6];
    const float* db1      = (const float*)d_in[7];
    const float* dW2      = (const float*)d_in[8];
    const float* db2      = (const float*)d_in[9];
    const float* dW3      = (const float*)d_in[10];
    const float* db3      = (const float*)d_in[11];
    const float* cW1      = (const float*)d_in[12];
    const float* cb1      = (const float*)d_in[13];
    const float* cW2      = (const float*)d_in[14];
    const float* cb2      = (const float*)d_in[15];
    const float* cW3      = (const float*)d_in[16];
    const float* cb3      = (const float*)d_in[17];
    const float* log_diff = (const float*)d_in[18];
    float* out = (float*)d_out;

    // Bf 2*64KB + baseR 2*32KB + wzR 2KB + b2R 1KB + W3R 2KB + psum 2KB + mbars 128B
    const int smemB = 2 * 65536 + 2 * 32768 + 512 * 4 + 256 * 4 + 512 * 4 + 256 * 8 + 128;
    cudaFuncSetAttribute(sde_kernel, cudaFuncAttributeMaxDynamicSharedMemorySize, smemB);

    prep_kernel<<<1, 128>>>(times, freqs, dW1, db1, cW1, cb1, log_diff, out);
    sde_kernel<<<N_SAMP / SPB, NTHREADS, smemB>>>(z0, pctx, cctx, noise,
                                                  dW1, dW2, db2, dW3, db3,
                                                  cW1, cW2, cb2, cW3, cb3, out);
}

// round 10
// speedup vs baseline: 1.3095x; 1.1618x over previous
#include <cuda_runtime.h>
#include <cuda_bf16.h>
#include <cuda_fp16.h>
#include <cstdint>

#define N_SAMP   262144
#define ZD       2
#define CTX      128
#define HID      128
#define TEMB     32
#define NSTEPS   50
#define SPB      64      // samples per block
#define NTHREADS 256     // 8 warps: 4 diffusion + 4 cnf, 16 samples each

// output layout: traj [51,N,2] | us [50,N,2] | times [51]
#define US_OFF    ((long long)(NSTEPS+1) * N_SAMP * ZD)
#define TAIL_OFF  (US_OFF + (long long)NSTEPS * N_SAMP * ZD)

// per-step constants, tw permuted into per-lane fragment order:
// idx = i*128 + kt*16 + t*4 + comp,  comp = reg*2 + half  (k = kt*16 + 2t + reg*8 + half)
__device__ float g_twd[NSTEPS * HID];
__device__ float g_twc[NSTEPS * HID];
__device__ float g_dts[NSTEPS];
__device__ float g_coef[NSTEPS];

// fast silu: x*sigmoid(x) = 0.5x + 0.5x*tanh(0.5x)  (1 MUFU.TANH)
__device__ __forceinline__ float fsilu(float x) {
    float h = 0.5f * x;
    float t;
    asm("tanh.approx.f32 %0, %1;" : "=f"(t) : "f"(h));
    return fmaf(h, t, h);
}
// pack two fp32 -> fp16x2: lower half = even-k val, upper half = odd-k val
__device__ __forceinline__ uint32_t cvt2h(float odd_k, float even_k) {
    uint32_t r; asm("cvt.rn.f16x2.f32 %0, %1, %2;" : "=r"(r) : "f"(odd_k), "f"(even_k)); return r;
}
__device__ __forceinline__ void mma16816h(float* d, uint32_t a0, uint32_t a1,
                                          uint32_t a2, uint32_t a3,
                                          uint32_t b0, uint32_t b1) {
    asm volatile("mma.sync.aligned.m16n8k16.row.col.f32.f16.f16.f32 "
                 "{%0,%1,%2,%3}, {%4,%5,%6,%7}, {%8,%9}, {%0,%1,%2,%3};"
                 : "+f"(d[0]), "+f"(d[1]), "+f"(d[2]), "+f"(d[3])
                 : "r"(a0), "r"(a1), "r"(a2), "r"(a3), "r"(b0), "r"(b1));
}
__device__ __forceinline__ void mbar_init(uint32_t addr, uint32_t cnt) {
    asm volatile("mbarrier.init.shared.b64 [%0], %1;" :: "r"(addr), "r"(cnt) : "memory");
}
__device__ __forceinline__ void mbar_arrive(uint32_t addr) {
    asm volatile("mbarrier.arrive.release.cta.shared::cta.b64 _, [%0];" :: "r"(addr) : "memory");
}
__device__ __forceinline__ void mbar_wait(uint32_t addr, uint32_t parity) {
    asm volatile("{\n\t"
                 ".reg .pred P1;\n\t"
                 "WAIT_%=:\n\t"
                 "mbarrier.try_wait.parity.acquire.cta.shared::cta.b64 P1, [%0], %1, 0x989680;\n\t"
                 "@P1 bra.uni DONE_%=;\n\t"
                 "bra.uni WAIT_%=;\n\t"
                 "DONE_%=:\n\t"
                 "}"
                 :: "r"(addr), "r"(parity) : "memory");
}

// fragment position helpers (k within 128): kt = k>>4, kr = k&15
// t = (kr&7)>>1, reg = (kr>>3)&1, half = kr&1, comp = reg*2 + half
__host__ __device__ __forceinline__ int frag_comp(int kr) { return (((kr >> 3) & 1) << 1) | (kr & 1); }

// ---------------------------------------------------------------------------
// Kernel A: per-step constants (temb @ W1_temb + b1 in permuted layout) + times tail
// ---------------------------------------------------------------------------
__global__ void prep_kernel(const float* __restrict__ times,
                            const float* __restrict__ freqs,
                            const float* __restrict__ dW1, const float* __restrict__ db1,
                            const float* __restrict__ cW1, const float* __restrict__ cb1,
                            const float* __restrict__ log_diff,
                            float* __restrict__ out)
{
    __shared__ float temb[TEMB];
    int tid = threadIdx.x;  // 128 threads, tid = k
    if (tid < NSTEPS + 1) out[TAIL_OFF + tid] = times[tid];
    int kt = tid >> 4, kr = tid & 15;
    int pidx = kt * 16 + ((kr & 7) >> 1) * 4 + frag_comp(kr);  // permuted position
    float gb = log1pf(__expf(log_diff[0]));  // softplus
    for (int i = 0; i < NSTEPS; i++) {
        float t = times[i];
        __syncthreads();
        if (tid < TEMB / 2) {
            float a = 6.2831853071795864f * t * freqs[tid];
            temb[tid]            = sinf(a);
            temb[tid + TEMB / 2] = cosf(a);
        }
        __syncthreads();
        float ad = db1[tid], ac = cb1[tid];
#pragma unroll 8
        for (int mm = 0; mm < TEMB; mm++) {
            float tv = temb[mm];
            ad += tv * dW1[(ZD + CTX + mm) * HID + tid];
            ac += tv * cW1[(ZD + CTX + mm) * HID + tid];
        }
        g_twd[i * HID + pidx] = ad;
        g_twc[i * HID + pidx] = ac;
        if (tid == 0) {
            float dt = times[i + 1] - t;
            g_dts[i]  = dt;
            g_coef[i] = gb * (1.0f - t) * sqrtf(fmaxf(dt, 1e-12f));
        }
    }
}

// ---------------------------------------------------------------------------
// base = ctx @ W1[2:130] for one group of 8 samples (old [s][k] layout)
// ---------------------------------------------------------------------------
__device__ __forceinline__ void compute_base(float* __restrict__ dst,
                                             const float* __restrict__ tmp,
                                             const float* __restrict__ W1,
                                             int grp, int l)
{
    float acc[8][4];
#pragma unroll
    for (int s8 = 0; s8 < 8; s8++)
#pragma unroll
        for (int c = 0; c < 4; c++) acc[s8][c] = 0.f;
#pragma unroll 2
    for (int r = 0; r < CTX; r++) {
        float w1v[4];
#pragma unroll
        for (int c = 0; c < 4; c++) w1v[c] = W1[(ZD + r) * HID + l + 32 * c];
#pragma unroll
        for (int s8 = 0; s8 < 8; s8++) {
            float a = tmp[(grp * 8 + s8) * HID + r];
#pragma unroll
            for (int c = 0; c < 4; c++) acc[s8][c] += a * w1v[c];
        }
    }
#pragma unroll
    for (int s8 = 0; s8 < 8; s8++)
#pragma unroll
        for (int c = 0; c < 4; c++)
            dst[(grp * 8 + s8) * HID + l + 32 * c] = acc[s8][c];
}

// ---------------------------------------------------------------------------
// Kernel B: persistent 50-step SDE, tensor-core layer-2 in fp16:
// A = single fp16 (silu outputs), B = fp16 hi+lo split of W2 -> 2 MMAs/tile.
// 256 threads, 8 warps. Warp map: m = w&1 (MLP), wg = w>>1 (sample group) so
// handshake partners (m0,wg)<->(m1,wg) sit on ADJACENT SMSPs and each SMSP
// hosts warps of different pairs (de-phasing possible).
// Step sync: pairwise mbarrier handshake, no CTA barrier in the loop.
// ---------------------------------------------------------------------------
__global__ void __launch_bounds__(NTHREADS, 1)
sde_kernel(const float* __restrict__ z0,
           const float* __restrict__ pctx, const float* __restrict__ cctx,
           const float* __restrict__ noise,
           const float* __restrict__ dW1, const float* __restrict__ dW2,
           const float* __restrict__ db2, const float* __restrict__ dW3,
           const float* __restrict__ db3,
           const float* __restrict__ cW1, const float* __restrict__ cW2,
           const float* __restrict__ cb2, const float* __restrict__ cW3,
           const float* __restrict__ cb3,
           float* __restrict__ out)
{
    extern __shared__ float sm[];
    uint4* BfD    = (uint4*)sm;              // 8kt*16ntg*32lane uint4 = 64KB
    uint4* BfC    = BfD + 4096;              // 64KB
    float* baseRD = (float*)(BfC + 4096);    // 4 wg * 2048 floats = 32KB
    float* baseRC = baseRD + 8192;           // 32KB
    float* wzRs   = baseRC + 8192;           // [mlp][row][kt][t] float4 = 512 f
    float* b2Rs   = wzRs + 512;              // [mlp][ntg][t] float2 = 256 f
    float* W3Rs   = b2Rs + 256;              // [mlp][ntg][t] float4 = 512 f
    float2* psum2 = (float2*)(W3Rs + 512);   // [2 buf][2 mlp][64] float2 = 2KB
    // mbarriers: [2 mlp][4 wg][2 buf] u64 = 128B
    unsigned long long* mbars = (unsigned long long*)(psum2 + 256);

    int tid = threadIdx.x;
    int w = tid >> 5, l = tid & 31;
    int m  = w & 1;        // 0 = diffusion (u), 1 = cnf (f)  [SMSP-aware map]
    int wg = w >> 1;       // sample group of 16
    int t3 = l & 3;        // quad thread
    int g  = l >> 2;       // row 0-7 (sample A); sample B = row g+8
    int blockBase = blockIdx.x * SPB;
    int sA = wg * 16 + g;
    int sB = sA + 8;
    int gsA = blockBase + sA;
    int gsB = blockBase + sB;

    // ================= phase 1 =================
    // 1) stage ctx tiles into the (not yet used) Bfrag regions
    {
        float* tD = (float*)BfD;
        float* tC = (float*)BfC;
        for (int idx = tid; idx < SPB * HID; idx += NTHREADS) {
            tD[idx] = pctx[(long long)blockBase * HID + idx];
            tC[idx] = cctx[(long long)blockBase * HID + idx];
        }
    }
    __syncthreads();
    // 2) base in old [s][k] layout: each MLP's 4 warps cover groups 0-7
    if (m == 0) {
        compute_base(baseRD, (float*)BfD, dW1, wg * 2,     l);
        compute_base(baseRD, (float*)BfD, dW1, wg * 2 + 1, l);
    } else {
        compute_base(baseRC, (float*)BfC, cW1, wg * 2,     l);
        compute_base(baseRC, (float*)BfC, cW1, wg * 2 + 1, l);
    }
    __syncthreads();
    // 3) in-place permute base -> fragment order:
    //    ni = ((swg*8 + kt)*32 + lane)*8 + hi8*4 + comp
    {
        float tmpv[32];
#pragma unroll
        for (int a = 0; a < 2; a++) {
            float* arr = a ? baseRC : baseRD;
#pragma unroll
            for (int q = 0; q < 32; q++) tmpv[q] = arr[tid * 32 + q];
            __syncthreads();
#pragma unroll
            for (int q = 0; q < 32; q++) {
                int idx = tid * 32 + q;
                int s = idx >> 7, k = idx & 127;
                int swg = s >> 4, srow = s & 15;
                int hi8 = srow >> 3, gg = srow & 7;
                int kt = k >> 4, kr = k & 15;
                int lane = gg * 4 + ((kr & 7) >> 1);
                int ni = ((swg * 8 + kt) * 32 + lane) * 8 + hi8 * 4 + frag_comp(kr);
                arr[ni] = tmpv[q];
            }
            __syncthreads();
        }
    }
    // 4) W2 -> fp16 hi/lo in B-fragment layout; plus small tables; mbarrier init
    {
        unsigned short* bD16 = (unsigned short*)BfD;
        unsigned short* bC16 = (unsigned short*)BfC;
        for (int e = tid; e < HID * HID; e += NTHREADS) {
            int k = e >> 7, j = e & 127;
            int kt = k >> 4, kr = k & 15;
            int reg = (kr >> 3) & 1, half = kr & 1;
            int lane = (j & 7) * 4 + ((kr & 7) >> 1);
            int ntg = j >> 3;
            int slot = (((kt * 16 + ntg) * 32 + lane) * 4);
            {
                float wv = dW2[e];
                __half hb = __float2half_rn(wv);
                __half lb = __float2half_rn(wv - __half2float(hb));
                bD16[(slot + reg) * 2 + half]     = __half_as_ushort(hb);
                bD16[(slot + 2 + reg) * 2 + half] = __half_as_ushort(lb);
            }
            {
                float wv = cW2[e];
                __half hb = __float2half_rn(wv);
                __half lb = __float2half_rn(wv - __half2float(hb));
                bC16[(slot + reg) * 2 + half]     = __half_as_ushort(hb);
                bC16[(slot + 2 + reg) * 2 + half] = __half_as_ushort(lb);
            }
        }
        // wzR: [mlp][row][kt][t][comp]
        for (int idx = tid; idx < 2 * 2 * HID; idx += NTHREADS) {
            int mlp = idx >> 8, row = (idx >> 7) & 1, k = idx & 127;
            int kt = k >> 4, kr = k & 15;
            float v = (mlp ? cW1 : dW1)[row * HID + k];
            wzRs[((mlp * 2 + row) * 8 + kt) * 16 + ((kr & 7) >> 1) * 4 + frag_comp(kr)] = v;
        }
        // b2R: [mlp][ntg][t][half]   (j = ntg*8 + 2t + half)
        for (int idx = tid; idx < 2 * HID; idx += NTHREADS) {
            int mlp = idx >> 7, j = idx & 127;
            float v = (mlp ? cb2 : db2)[j];
            b2Rs[(mlp * 16 + (j >> 3)) * 8 + ((j & 7) >> 1) * 2 + (j & 1)] = v;
        }
        // W3R: [mlp][ntg][t][(j&1)*2 + d]
        for (int idx = tid; idx < 2 * HID * ZD; idx += NTHREADS) {
            int mlp = idx >> 8, j = (idx >> 1) & 127, d = idx & 1;
            float v = (mlp ? cW3 : dW3)[j * ZD + d];
            W3Rs[(mlp * 16 + (j >> 3)) * 16 + ((j & 7) >> 1) * 4 + (j & 1) * 2 + d] = v;
        }
        // 16 mbarriers, arrive count = 8 (the t3==0 lanes of one warp)
        if (tid < 16)
            mbar_init((uint32_t)__cvta_generic_to_shared(&mbars[tid]), 8);
    }
    __syncthreads();

    // ================= per-warp constant pointers / regs =================
    const uint4*  Bf    = m ? BfC : BfD;
    const float4* bR4   = (const float4*)(m ? baseRC : baseRD);
    const float4* twR4  = (const float4*)(m ? g_twc : g_twd);
    const float4* wz04  = (const float4*)wzRs + (m * 2 + 0) * 32;
    const float4* wz14  = (const float4*)wzRs + (m * 2 + 1) * 32;
    const float2* b2R2  = (const float2*)b2Rs + m * 64;
    const float4* W3R4  = (const float4*)W3Rs + m * 64;
    const float2* noise2 = (const float2*)noise;
    float2* outTraj = (float2*)out;
    float2* outUS   = (float2*)(out + US_OFF);

    // my mbar (arrive) and partner mbar (wait), per buffer
    uint32_t myBar0   = (uint32_t)__cvta_generic_to_shared(&mbars[(m * 4 + wg) * 2 + 0]);
    uint32_t myBar1   = (uint32_t)__cvta_generic_to_shared(&mbars[(m * 4 + wg) * 2 + 1]);
    uint32_t peerBar0 = (uint32_t)__cvta_generic_to_shared(&mbars[((1 - m) * 4 + wg) * 2 + 0]);
    uint32_t peerBar1 = (uint32_t)__cvta_generic_to_shared(&mbars[((1 - m) * 4 + wg) * 2 + 1]);

    float b3_0, b3_1;
    { const float* b3 = m ? cb3 : db3; b3_0 = b3[0]; b3_1 = b3[1]; }

    // init z (all 4 lanes of quad hold both samples' z)
    float2 ziA = __ldg(&((const float2*)z0)[gsA]);
    float2 ziB = __ldg(&((const float2*)z0)[gsB]);
    float zA0 = ziA.x, zA1 = ziA.y, zB0 = ziB.x, zB1 = ziB.y;
    if (m == 1 && t3 == 0) { outTraj[gsA] = ziA; outTraj[gsB] = ziB; }

    // ================= 50-step loop (no CTA barrier inside) =================
    for (int i = 0; i < NSTEPS; i++) {
        float dt = g_dts[i], cf = g_coef[i];
        long long io = (long long)i * N_SAMP;
        float2 xiA = __ldg(&noise2[io + gsA]);
        float2 xiB = __ldg(&noise2[io + gsB]);

        float d[16][4];
#pragma unroll
        for (int nt = 0; nt < 16; nt++)
#pragma unroll
            for (int c = 0; c < 4; c++) d[nt][c] = 0.f;

        // ---- fused layer-1 (A frags fp16 in regs) + fp16 tensor layer-2 ----
#pragma unroll
        for (int kt = 0; kt < 8; kt++) {
            float4 bsA = bR4[((wg * 8 + kt) * 32 + l) * 2 + 0];
            float4 bsB = bR4[((wg * 8 + kt) * 32 + l) * 2 + 1];
            float4 tw  = __ldg(&twR4[i * 32 + kt * 4 + t3]);
            float4 w0  = wz04[kt * 4 + t3];
            float4 w1  = wz14[kt * 4 + t3];
            float hAx = fsilu(bsA.x + tw.x + zA0 * w0.x + zA1 * w1.x);
            float hAy = fsilu(bsA.y + tw.y + zA0 * w0.y + zA1 * w1.y);
            float hAz = fsilu(bsA.z + tw.z + zA0 * w0.z + zA1 * w1.z);
            float hAw = fsilu(bsA.w + tw.w + zA0 * w0.w + zA1 * w1.w);
            float hBx = fsilu(bsB.x + tw.x + zB0 * w0.x + zB1 * w1.x);
            float hBy = fsilu(bsB.y + tw.y + zB0 * w0.y + zB1 * w1.y);
            float hBz = fsilu(bsB.z + tw.z + zB0 * w0.z + zB1 * w1.z);
            float hBw = fsilu(bsB.w + tw.w + zB0 * w0.w + zB1 * w1.w);
            uint32_t a0 = cvt2h(hAy, hAx);
            uint32_t a1 = cvt2h(hBy, hBx);
            uint32_t a2 = cvt2h(hAw, hAz);
            uint32_t a3 = cvt2h(hBw, hBz);
#pragma unroll
            for (int ntc = 0; ntc < 16; ntc += 4) {
                uint4 Bv[4];
#pragma unroll
                for (int q = 0; q < 4; q++)
                    Bv[q] = Bf[(kt * 16 + ntc + q) * 32 + l];
#pragma unroll
                for (int q = 0; q < 4; q++)
                    mma16816h(d[ntc + q], a0, a1, a2, a3, Bv[q].x, Bv[q].y);
#pragma unroll
                for (int q = 0; q < 4; q++)
                    mma16816h(d[ntc + q], a0, a1, a2, a3, Bv[q].z, Bv[q].w);
            }
        }

        // ---- epilogue: silu(h2+b2), layer-3 partials (both samples) ----
        float aA0 = 0.f, aA1 = 0.f, aB0 = 0.f, aB1 = 0.f;
#pragma unroll
        for (int ntg = 0; ntg < 16; ntg++) {
            float2 b2v = b2R2[ntg * 4 + t3];
            float4 w3v = W3R4[ntg * 4 + t3];
            float x0 = fsilu(d[ntg][0] + b2v.x);
            float x1 = fsilu(d[ntg][1] + b2v.y);
            float x2 = fsilu(d[ntg][2] + b2v.x);
            float x3 = fsilu(d[ntg][3] + b2v.y);
            aA0 += x0 * w3v.x + x1 * w3v.z;
            aA1 += x0 * w3v.y + x1 * w3v.w;
            aB0 += x2 * w3v.x + x3 * w3v.z;
            aB1 += x2 * w3v.y + x3 * w3v.w;
        }

        // ---- quad reduction (all lanes get sums) ----
        aA0 += __shfl_xor_sync(0xffffffffu, aA0, 1);
        aA1 += __shfl_xor_sync(0xffffffffu, aA1, 1);
        aB0 += __shfl_xor_sync(0xffffffffu, aB0, 1);
        aB1 += __shfl_xor_sync(0xffffffffu, aB1, 1);
        aA0 += __shfl_xor_sync(0xffffffffu, aA0, 2);
        aA1 += __shfl_xor_sync(0xffffffffu, aA1, 2);
        aB0 += __shfl_xor_sync(0xffffffffu, aB0, 2);
        aB1 += __shfl_xor_sync(0xffffffffu, aB1, 2);
        float vA0 = aA0 + b3_0, vA1 = aA1 + b3_1;
        float vB0 = aB0 + b3_0, vB1 = aB1 + b3_1;

        // ---- pairwise mbarrier exchange (double-buffered) ----
        int buf = i & 1;
        uint32_t par = (i >> 1) & 1;
        int bufo = buf * 128;
        if (t3 == 0) {
            psum2[bufo + m * 64 + sA] = make_float2(vA0, vA1);
            psum2[bufo + m * 64 + sB] = make_float2(vB0, vB1);
            mbar_arrive(buf ? myBar1 : myBar0);
        }
        mbar_wait(buf ? peerBar1 : peerBar0, par);
        float2 ovA = psum2[bufo + (1 - m) * 64 + sA];
        float2 ovB = psum2[bufo + (1 - m) * 64 + sB];

        zA0 += (vA0 + ovA.x) * dt + xiA.x * cf;
        zA1 += (vA1 + ovA.y) * dt + xiA.y * cf;
        zB0 += (vB0 + ovB.x) * dt + xiB.x * cf;
        zB1 += (vB1 + ovB.y) * dt + xiB.y * cf;
        if (t3 == 0) {
            if (m == 0) {
                outUS[io + gsA] = make_float2(vA0, vA1);
                outUS[io + gsB] = make_float2(vB0, vB1);
            } else {
                outTraj[(long long)(i + 1) * N_SAMP + gsA] = make_float2(zA0, zA1);
                outTraj[(long long)(i + 1) * N_SAMP + gsB] = make_float2(zB0, zB1);
            }
        }
    }
}

// ---------------------------------------------------------------------------
extern "C" void kernel_launch(void* const* d_in, const int* in_sizes, int n_in,
                              void* d_out, int out_size)
{
    const float* z0       = (const float*)d_in[0];
    const float* pctx     = (const float*)d_in[1];
    const float* cctx     = (const float*)d_in[2];
    const float* times    = (const float*)d_in[3];
    const float* noise    = (const float*)d_in[4];
    const float* freqs    = (const float*)d_in[5];
    const float* dW1      = (const float*)d_in[6];
    const float* db1      = (const float*)d_in[7];
    const float* dW2      = (const float*)d_in[8];
    const float* db2      = (const float*)d_in[9];
    const float* dW3      = (const float*)d_in[10];
    const float* db3      = (const float*)d_in[11];
    const float* cW1      = (const float*)d_in[12];
    const float* cb1      = (const float*)d_in[13];
    const float* cW2      = (const float*)d_in[14];
    const float* cb2      = (const float*)d_in[15];
    const float* cW3      = (const float*)d_in[16];
    const float* cb3      = (const float*)d_in[17];
    const float* log_diff = (const float*)d_in[18];
    float* out = (float*)d_out;

    // Bf 2*64KB + baseR 2*32KB + wzR 2KB + b2R 1KB + W3R 2KB + psum 2KB + mbars 128B
    const int smemB = 2 * 65536 + 2 * 32768 + 512 * 4 + 256 * 4 + 512 * 4 + 256 * 8 + 128;
    cudaFuncSetAttribute(sde_kernel, cudaFuncAttributeMaxDynamicSharedMemorySize, smemB);

    prep_kernel<<<1, 128>>>(times, freqs, dW1, db1, cW1, cb1, log_diff, out);
    sde_kernel<<<N_SAMP / SPB, NTHREADS, smemB>>>(z0, pctx, cctx, noise,
                                                  dW1, dW2, db2, dW3, db3,
                                                  cW1, cW2, cb2, cW3, cb3, out);
}

// round 11
// speedup vs baseline: 1.7230x; 1.3158x over previous
#include <cuda_runtime.h>
#include <cuda_bf16.h>
#include <cuda_fp16.h>
#include <cstdint>

#define N_SAMP   262144
#define ZD       2
#define CTX      128
#define HID      128
#define TEMB     32
#define NSTEPS   50
#define SPB      64      // samples per block
#define NTHREADS 256     // 8 warps: 4 diffusion + 4 cnf, 16 samples each

// output layout: traj [51,N,2] | us [50,N,2] | times [51]
#define US_OFF    ((long long)(NSTEPS+1) * N_SAMP * ZD)
#define TAIL_OFF  (US_OFF + (long long)NSTEPS * N_SAMP * ZD)

// per-step constants, tw permuted into per-lane fragment order:
// idx = i*128 + kt*16 + t*4 + comp,  comp = reg*2 + half  (k = kt*16 + 2t + reg*8 + half)
__device__ float g_twd[NSTEPS * HID];
__device__ float g_twc[NSTEPS * HID];
__device__ float g_dts[NSTEPS];
__device__ float g_coef[NSTEPS];

// fast silu: x*sigmoid(x) = 0.5x + 0.5x*tanh(0.5x)  (1 MUFU.TANH)
__device__ __forceinline__ float fsilu(float x) {
    float h = 0.5f * x;
    float t;
    asm("tanh.approx.f32 %0, %1;" : "=f"(t) : "f"(h));
    return fmaf(h, t, h);
}
// pack two fp32 -> fp16x2: lower half = even-k val, upper half = odd-k val
__device__ __forceinline__ uint32_t cvt2h(float odd_k, float even_k) {
    uint32_t r; asm("cvt.rn.f16x2.f32 %0, %1, %2;" : "=r"(r) : "f"(odd_k), "f"(even_k)); return r;
}
__device__ __forceinline__ void mma16816h(float* d, uint32_t a0, uint32_t a1,
                                          uint32_t a2, uint32_t a3,
                                          uint32_t b0, uint32_t b1) {
    asm volatile("mma.sync.aligned.m16n8k16.row.col.f32.f16.f16.f32 "
                 "{%0,%1,%2,%3}, {%4,%5,%6,%7}, {%8,%9}, {%0,%1,%2,%3};"
                 : "+f"(d[0]), "+f"(d[1]), "+f"(d[2]), "+f"(d[3])
                 : "r"(a0), "r"(a1), "r"(a2), "r"(a3), "r"(b0), "r"(b1));
}
__device__ __forceinline__ void mbar_init(uint32_t addr, uint32_t cnt) {
    asm volatile("mbarrier.init.shared.b64 [%0], %1;" :: "r"(addr), "r"(cnt) : "memory");
}
__device__ __forceinline__ void mbar_arrive(uint32_t addr) {
    asm volatile("mbarrier.arrive.release.cta.shared::cta.b64 _, [%0];" :: "r"(addr) : "memory");
}
__device__ __forceinline__ void mbar_wait(uint32_t addr, uint32_t parity) {
    asm volatile("{\n\t"
                 ".reg .pred P1;\n\t"
                 "WAIT_%=:\n\t"
                 "mbarrier.try_wait.parity.acquire.cta.shared::cta.b64 P1, [%0], %1, 0x989680;\n\t"
                 "@P1 bra.uni DONE_%=;\n\t"
                 "bra.uni WAIT_%=;\n\t"
                 "DONE_%=:\n\t"
                 "}"
                 :: "r"(addr), "r"(parity) : "memory");
}

// fragment position helpers (k within 128): kt = k>>4, kr = k&15
// t = (kr&7)>>1, reg = (kr>>3)&1, half = kr&1, comp = reg*2 + half
__host__ __device__ __forceinline__ int frag_comp(int kr) { return (((kr >> 3) & 1) << 1) | (kr & 1); }

// ---------------------------------------------------------------------------
// Kernel A: per-step constants (temb @ W1_temb + b1 in permuted layout) + times tail
// ---------------------------------------------------------------------------
__global__ void prep_kernel(const float* __restrict__ times,
                            const float* __restrict__ freqs,
                            const float* __restrict__ dW1, const float* __restrict__ db1,
                            const float* __restrict__ cW1, const float* __restrict__ cb1,
                            const float* __restrict__ log_diff,
                            float* __restrict__ out)
{
    __shared__ float temb[TEMB];
    int tid = threadIdx.x;  // 128 threads, tid = k
    if (tid < NSTEPS + 1) out[TAIL_OFF + tid] = times[tid];
    int kt = tid >> 4, kr = tid & 15;
    int pidx = kt * 16 + ((kr & 7) >> 1) * 4 + frag_comp(kr);  // permuted position
    float gb = log1pf(__expf(log_diff[0]));  // softplus
    for (int i = 0; i < NSTEPS; i++) {
        float t = times[i];
        __syncthreads();
        if (tid < TEMB / 2) {
            float a = 6.2831853071795864f * t * freqs[tid];
            temb[tid]            = sinf(a);
            temb[tid + TEMB / 2] = cosf(a);
        }
        __syncthreads();
        float ad = db1[tid], ac = cb1[tid];
#pragma unroll 8
        for (int mm = 0; mm < TEMB; mm++) {
            float tv = temb[mm];
            ad += tv * dW1[(ZD + CTX + mm) * HID + tid];
            ac += tv * cW1[(ZD + CTX + mm) * HID + tid];
        }
        g_twd[i * HID + pidx] = ad;
        g_twc[i * HID + pidx] = ac;
        if (tid == 0) {
            float dt = times[i + 1] - t;
            g_dts[i]  = dt;
            g_coef[i] = gb * (1.0f - t) * sqrtf(fmaxf(dt, 1e-12f));
        }
    }
}

// ---------------------------------------------------------------------------
// base = ctx @ W1[2:130] for one group of 8 samples (old [s][k] layout)
// ---------------------------------------------------------------------------
__device__ __forceinline__ void compute_base(float* __restrict__ dst,
                                             const float* __restrict__ tmp,
                                             const float* __restrict__ W1,
                                             int grp, int l)
{
    float acc[8][4];
#pragma unroll
    for (int s8 = 0; s8 < 8; s8++)
#pragma unroll
        for (int c = 0; c < 4; c++) acc[s8][c] = 0.f;
#pragma unroll 2
    for (int r = 0; r < CTX; r++) {
        float w1v[4];
#pragma unroll
        for (int c = 0; c < 4; c++) w1v[c] = W1[(ZD + r) * HID + l + 32 * c];
#pragma unroll
        for (int s8 = 0; s8 < 8; s8++) {
            float a = tmp[(grp * 8 + s8) * HID + r];
#pragma unroll
            for (int c = 0; c < 4; c++) acc[s8][c] += a * w1v[c];
        }
    }
#pragma unroll
    for (int s8 = 0; s8 < 8; s8++)
#pragma unroll
        for (int c = 0; c < 4; c++)
            dst[(grp * 8 + s8) * HID + l + 32 * c] = acc[s8][c];
}

// ---------------------------------------------------------------------------
// Kernel B: persistent 50-step SDE, fp16 tensor-core layer-2.
// A = fp16 silu outputs, B = SINGLE fp16 W2 -> 1 MMA per (kt,ntg) tile,
// one LDS.128 feeds TWO n-tiles: Bv = {b0,b1}(ntg even), {b0,b1}(ntg odd).
// 256 threads, 8 warps. Warp map: m = w&1 (MLP), wg = w>>1 (sample group).
// Step sync: pairwise mbarrier handshake, no CTA barrier in the loop.
// SMEM: BfD(32K) BfC(32K) baseRD(32K) baseRC(32K) + tables + psum ≈ 135KB.
// ---------------------------------------------------------------------------
__global__ void __launch_bounds__(NTHREADS, 1)
sde_kernel(const float* __restrict__ z0,
           const float* __restrict__ pctx, const float* __restrict__ cctx,
           const float* __restrict__ noise,
           const float* __restrict__ dW1, const float* __restrict__ dW2,
           const float* __restrict__ db2, const float* __restrict__ dW3,
           const float* __restrict__ db3,
           const float* __restrict__ cW1, const float* __restrict__ cW2,
           const float* __restrict__ cb2, const float* __restrict__ cW3,
           const float* __restrict__ cb3,
           float* __restrict__ out)
{
    extern __shared__ float sm[];
    uint4* BfD    = (uint4*)sm;              // 8kt*8ntp*32lane uint4 = 32KB
    uint4* BfC    = BfD + 2048;              // 32KB
    float* baseRD = (float*)(BfC + 2048);    // 4 wg * 2048 floats = 32KB
    float* baseRC = baseRD + 8192;           // 32KB
    float* wzRs   = baseRC + 8192;           // [mlp][row][kt][t] float4 = 512 f
    float* b2Rs   = wzRs + 512;              // [mlp][ntg][t] float2 = 256 f
    float* W3Rs   = b2Rs + 256;              // [mlp][ntg][t] float4 = 512 f
    float2* psum2 = (float2*)(W3Rs + 512);   // [2 buf][2 mlp][64] float2 = 2KB
    // mbarriers: [2 mlp][4 wg][2 buf] u64 = 128B
    unsigned long long* mbars = (unsigned long long*)(psum2 + 256);

    int tid = threadIdx.x;
    int w = tid >> 5, l = tid & 31;
    int m  = w & 1;        // 0 = diffusion (u), 1 = cnf (f)  [SMSP-aware map]
    int wg = w >> 1;       // sample group of 16
    int t3 = l & 3;        // quad thread
    int g  = l >> 2;       // row 0-7 (sample A); sample B = row g+8
    int blockBase = blockIdx.x * SPB;
    int sA = wg * 16 + g;
    int sB = sA + 8;
    int gsA = blockBase + sA;
    int gsB = blockBase + sB;

    // ================= phase 1 =================
    // 1) stage ctx tiles into the (not yet used) Bfrag regions (32KB each, exact fit)
    {
        float* tD = (float*)BfD;
        float* tC = (float*)BfC;
        for (int idx = tid; idx < SPB * HID; idx += NTHREADS) {
            tD[idx] = pctx[(long long)blockBase * HID + idx];
            tC[idx] = cctx[(long long)blockBase * HID + idx];
        }
    }
    __syncthreads();
    // 2) base in old [s][k] layout: each MLP's 4 warps cover groups 0-7
    if (m == 0) {
        compute_base(baseRD, (float*)BfD, dW1, wg * 2,     l);
        compute_base(baseRD, (float*)BfD, dW1, wg * 2 + 1, l);
    } else {
        compute_base(baseRC, (float*)BfC, cW1, wg * 2,     l);
        compute_base(baseRC, (float*)BfC, cW1, wg * 2 + 1, l);
    }
    __syncthreads();
    // 3) in-place permute base -> fragment order:
    //    ni = ((swg*8 + kt)*32 + lane)*8 + hi8*4 + comp
    {
        float tmpv[32];
#pragma unroll
        for (int a = 0; a < 2; a++) {
            float* arr = a ? baseRC : baseRD;
#pragma unroll
            for (int q = 0; q < 32; q++) tmpv[q] = arr[tid * 32 + q];
            __syncthreads();
#pragma unroll
            for (int q = 0; q < 32; q++) {
                int idx = tid * 32 + q;
                int s = idx >> 7, k = idx & 127;
                int swg = s >> 4, srow = s & 15;
                int hi8 = srow >> 3, gg = srow & 7;
                int kt = k >> 4, kr = k & 15;
                int lane = gg * 4 + ((kr & 7) >> 1);
                int ni = ((swg * 8 + kt) * 32 + lane) * 8 + hi8 * 4 + frag_comp(kr);
                arr[ni] = tmpv[q];
            }
            __syncthreads();
        }
    }
    // 4) W2 -> SINGLE fp16 in B-fragment layout (two ntg per uint4); tables; mbars
    {
        unsigned short* bD16 = (unsigned short*)BfD;
        unsigned short* bC16 = (unsigned short*)BfC;
        for (int e = tid; e < HID * HID; e += NTHREADS) {
            int k = e >> 7, j = e & 127;
            int kt = k >> 4, kr = k & 15;
            int reg = (kr >> 3) & 1, half = kr & 1;
            int lane = (j & 7) * 4 + ((kr & 7) >> 1);
            int ntg = j >> 3;
            int ntp = ntg >> 1, sub = ntg & 1;
            // word slot within 32-bit array; uint4 covers 4 words (2 ntg x 2 regs)
            int slot = ((kt * 8 + ntp) * 32 + lane) * 4 + sub * 2 + reg;
            bD16[slot * 2 + half] = __half_as_ushort(__float2half_rn(dW2[e]));
            bC16[slot * 2 + half] = __half_as_ushort(__float2half_rn(cW2[e]));
        }
        // wzR: [mlp][row][kt][t][comp]
        for (int idx = tid; idx < 2 * 2 * HID; idx += NTHREADS) {
            int mlp = idx >> 8, row = (idx >> 7) & 1, k = idx & 127;
            int kt = k >> 4, kr = k & 15;
            float v = (mlp ? cW1 : dW1)[row * HID + k];
            wzRs[((mlp * 2 + row) * 8 + kt) * 16 + ((kr & 7) >> 1) * 4 + frag_comp(kr)] = v;
        }
        // b2R: [mlp][ntg][t][half]   (j = ntg*8 + 2t + half)
        for (int idx = tid; idx < 2 * HID; idx += NTHREADS) {
            int mlp = idx >> 7, j = idx & 127;
            float v = (mlp ? cb2 : db2)[j];
            b2Rs[(mlp * 16 + (j >> 3)) * 8 + ((j & 7) >> 1) * 2 + (j & 1)] = v;
        }
        // W3R: [mlp][ntg][t][(j&1)*2 + d]
        for (int idx = tid; idx < 2 * HID * ZD; idx += NTHREADS) {
            int mlp = idx >> 8, j = (idx >> 1) & 127, d = idx & 1;
            float v = (mlp ? cW3 : dW3)[j * ZD + d];
            W3Rs[(mlp * 16 + (j >> 3)) * 16 + ((j & 7) >> 1) * 4 + (j & 1) * 2 + d] = v;
        }
        // 16 mbarriers, arrive count = 8 (the t3==0 lanes of one warp)
        if (tid < 16)
            mbar_init((uint32_t)__cvta_generic_to_shared(&mbars[tid]), 8);
    }
    __syncthreads();

    // ================= per-warp constant pointers / regs =================
    const uint4*  Bf    = m ? BfC : BfD;
    const float4* bR4   = (const float4*)(m ? baseRC : baseRD);
    const float4* twR4  = (const float4*)(m ? g_twc : g_twd);
    const float4* wz04  = (const float4*)wzRs + (m * 2 + 0) * 32;
    const float4* wz14  = (const float4*)wzRs + (m * 2 + 1) * 32;
    const float2* b2R2  = (const float2*)b2Rs + m * 64;
    const float4* W3R4  = (const float4*)W3Rs + m * 64;
    const float2* noise2 = (const float2*)noise;
    float2* outTraj = (float2*)out;
    float2* outUS   = (float2*)(out + US_OFF);

    // my mbar (arrive) and partner mbar (wait), per buffer
    uint32_t myBar0   = (uint32_t)__cvta_generic_to_shared(&mbars[(m * 4 + wg) * 2 + 0]);
    uint32_t myBar1   = (uint32_t)__cvta_generic_to_shared(&mbars[(m * 4 + wg) * 2 + 1]);
    uint32_t peerBar0 = (uint32_t)__cvta_generic_to_shared(&mbars[((1 - m) * 4 + wg) * 2 + 0]);
    uint32_t peerBar1 = (uint32_t)__cvta_generic_to_shared(&mbars[((1 - m) * 4 + wg) * 2 + 1]);

    float b3_0, b3_1;
    { const float* b3 = m ? cb3 : db3; b3_0 = b3[0]; b3_1 = b3[1]; }

    // init z (all 4 lanes of quad hold both samples' z)
    float2 ziA = __ldg(&((const float2*)z0)[gsA]);
    float2 ziB = __ldg(&((const float2*)z0)[gsB]);
    float zA0 = ziA.x, zA1 = ziA.y, zB0 = ziB.x, zB1 = ziB.y;
    if (m == 1 && t3 == 0) { outTraj[gsA] = ziA; outTraj[gsB] = ziB; }

    // ================= 50-step loop (no CTA barrier inside) =================
    for (int i = 0; i < NSTEPS; i++) {
        float dt = g_dts[i], cf = g_coef[i];
        long long io = (long long)i * N_SAMP;
        float2 xiA = __ldg(&noise2[io + gsA]);
        float2 xiB = __ldg(&noise2[io + gsB]);

        float d[16][4];
#pragma unroll
        for (int nt = 0; nt < 16; nt++)
#pragma unroll
            for (int c = 0; c < 4; c++) d[nt][c] = 0.f;

        // ---- fused layer-1 (A frags fp16 in regs) + fp16 tensor layer-2 ----
#pragma unroll
        for (int kt = 0; kt < 8; kt++) {
            float4 bsA = bR4[((wg * 8 + kt) * 32 + l) * 2 + 0];
            float4 bsB = bR4[((wg * 8 + kt) * 32 + l) * 2 + 1];
            float4 tw  = __ldg(&twR4[i * 32 + kt * 4 + t3]);
            float4 w0  = wz04[kt * 4 + t3];
            float4 w1  = wz14[kt * 4 + t3];
            float hAx = fsilu(bsA.x + tw.x + zA0 * w0.x + zA1 * w1.x);
            float hAy = fsilu(bsA.y + tw.y + zA0 * w0.y + zA1 * w1.y);
            float hAz = fsilu(bsA.z + tw.z + zA0 * w0.z + zA1 * w1.z);
            float hAw = fsilu(bsA.w + tw.w + zA0 * w0.w + zA1 * w1.w);
            float hBx = fsilu(bsB.x + tw.x + zB0 * w0.x + zB1 * w1.x);
            float hBy = fsilu(bsB.y + tw.y + zB0 * w0.y + zB1 * w1.y);
            float hBz = fsilu(bsB.z + tw.z + zB0 * w0.z + zB1 * w1.z);
            float hBw = fsilu(bsB.w + tw.w + zB0 * w0.w + zB1 * w1.w);
            uint32_t a0 = cvt2h(hAy, hAx);
            uint32_t a1 = cvt2h(hBy, hBx);
            uint32_t a2 = cvt2h(hAw, hAz);
            uint32_t a3 = cvt2h(hBw, hBz);
#pragma unroll
            for (int ntp = 0; ntp < 8; ntp += 4) {
                uint4 Bv[4];
#pragma unroll
                for (int q = 0; q < 4; q++)
                    Bv[q] = Bf[(kt * 8 + ntp + q) * 32 + l];
#pragma unroll
                for (int q = 0; q < 4; q++) {
                    mma16816h(d[(ntp + q) * 2 + 0], a0, a1, a2, a3, Bv[q].x, Bv[q].y);
                    mma16816h(d[(ntp + q) * 2 + 1], a0, a1, a2, a3, Bv[q].z, Bv[q].w);
                }
            }
        }

        // ---- epilogue: silu(h2+b2), layer-3 partials (both samples) ----
        float aA0 = 0.f, aA1 = 0.f, aB0 = 0.f, aB1 = 0.f;
#pragma unroll
        for (int ntg = 0; ntg < 16; ntg++) {
            float2 b2v = b2R2[ntg * 4 + t3];
            float4 w3v = W3R4[ntg * 4 + t3];
            float x0 = fsilu(d[ntg][0] + b2v.x);
            float x1 = fsilu(d[ntg][1] + b2v.y);
            float x2 = fsilu(d[ntg][2] + b2v.x);
            float x3 = fsilu(d[ntg][3] + b2v.y);
            aA0 += x0 * w3v.x + x1 * w3v.z;
            aA1 += x0 * w3v.y + x1 * w3v.w;
            aB0 += x2 * w3v.x + x3 * w3v.z;
            aB1 += x2 * w3v.y + x3 * w3v.w;
        }

        // ---- quad reduction (all lanes get sums) ----
        aA0 += __shfl_xor_sync(0xffffffffu, aA0, 1);
        aA1 += __shfl_xor_sync(0xffffffffu, aA1, 1);
        aB0 += __shfl_xor_sync(0xffffffffu, aB0, 1);
        aB1 += __shfl_xor_sync(0xffffffffu, aB1, 1);
        aA0 += __shfl_xor_sync(0xffffffffu, aA0, 2);
        aA1 += __shfl_xor_sync(0xffffffffu, aA1, 2);
        aB0 += __shfl_xor_sync(0xffffffffu, aB0, 2);
        aB1 += __shfl_xor_sync(0xffffffffu, aB1, 2);
        float vA0 = aA0 + b3_0, vA1 = aA1 + b3_1;
        float vB0 = aB0 + b3_0, vB1 = aB1 + b3_1;

        // ---- pairwise mbarrier exchange (double-buffered) ----
        int buf = i & 1;
        uint32_t par = (i >> 1) & 1;
        int bufo = buf * 128;
        if (t3 == 0) {
            psum2[bufo + m * 64 + sA] = make_float2(vA0, vA1);
            psum2[bufo + m * 64 + sB] = make_float2(vB0, vB1);
            mbar_arrive(buf ? myBar1 : myBar0);
        }
        mbar_wait(buf ? peerBar1 : peerBar0, par);
        float2 ovA = psum2[bufo + (1 - m) * 64 + sA];
        float2 ovB = psum2[bufo + (1 - m) * 64 + sB];

        zA0 += (vA0 + ovA.x) * dt + xiA.x * cf;
        zA1 += (vA1 + ovA.y) * dt + xiA.y * cf;
        zB0 += (vB0 + ovB.x) * dt + xiB.x * cf;
        zB1 += (vB1 + ovB.y) * dt + xiB.y * cf;
        if (t3 == 0) {
            if (m == 0) {
                outUS[io + gsA] = make_float2(vA0, vA1);
                outUS[io + gsB] = make_float2(vB0, vB1);
            } else {
                outTraj[(long long)(i + 1) * N_SAMP + gsA] = make_float2(zA0, zA1);
                outTraj[(long long)(i + 1) * N_SAMP + gsB] = make_float2(zB0, zB1);
            }
        }
    }
}

// ---------------------------------------------------------------------------
extern "C" void kernel_launch(void* const* d_in, const int* in_sizes, int n_in,
                              void* d_out, int out_size)
{
    const float* z0       = (const float*)d_in[0];
    const float* pctx     = (const float*)d_in[1];
    const float* cctx     = (const float*)d_in[2];
    const float* times    = (const float*)d_in[3];
    const float* noise    = (const float*)d_in[4];
    const float* freqs    = (const float*)d_in[5];
    const float* dW1      = (const float*)d_in[6];
    const float* db1      = (const float*)d_in[7];
    const float* dW2      = (const float*)d_in[8];
    const float* db2      = (const float*)d_in[9];
    const float* dW3      = (const float*)d_in[10];
    const float* db3      = (const float*)d_in[11];
    const float* cW1      = (const float*)d_in[12];
    const float* cb1      = (const float*)d_in[13];
    const float* cW2      = (const float*)d_in[14];
    const float* cb2      = (const float*)d_in[15];
    const float* cW3      = (const float*)d_in[16];
    const float* cb3      = (const float*)d_in[17];
    const float* log_diff = (const float*)d_in[18];
    float* out = (float*)d_out;

    // Bf 2*32KB + baseR 2*32KB + wzR 2KB + b2R 1KB + W3R 2KB + psum 2KB + mbars 128B
    const int smemB = 2 * 32768 + 2 * 32768 + 512 * 4 + 256 * 4 + 512 * 4 + 256 * 8 + 128;
    cudaFuncSetAttribute(sde_kernel, cudaFuncAttributeMaxDynamicSharedMemorySize, smemB);

    prep_kernel<<<1, 128>>>(times, freqs, dW1, db1, cW1, cb1, log_diff, out);
    sde_kernel<<<N_SAMP / SPB, NTHREADS, smemB>>>(z0, pctx, cctx, noise,
                                                  dW1, dW2, db2, dW3, db3,
                                                  cW1, cW2, cb2, cW3, cb3, out);
}

// round 12
// speedup vs baseline: 1.9596x; 1.1373x over previous
#include <cuda_runtime.h>
#include <cuda_bf16.h>
#include <cuda_fp16.h>
#include <cstdint>

#define N_SAMP   262144
#define ZD       2
#define CTX      128
#define HID      128
#define TEMB     32
#define NSTEPS   50
#define SPB      128     // samples per block
#define NTHREADS 512     // 16 warps: 8 diffusion + 8 cnf, 16 samples each

// output layout: traj [51,N,2] | us [50,N,2] | times [51]
#define US_OFF    ((long long)(NSTEPS+1) * N_SAMP * ZD)
#define TAIL_OFF  (US_OFF + (long long)NSTEPS * N_SAMP * ZD)

// per-step constants, tw permuted into per-lane fragment order:
// idx = i*128 + kt*16 + t*4 + comp,  comp = reg*2 + half  (k = kt*16 + 2t + reg*8 + half)
__device__ float g_twd[NSTEPS * HID];
__device__ float g_twc[NSTEPS * HID];
__device__ float g_dts[NSTEPS];
__device__ float g_coef[NSTEPS];

// fast silu: x*sigmoid(x) = 0.5x + 0.5x*tanh(0.5x)  (1 MUFU.TANH)
__device__ __forceinline__ float fsilu(float x) {
    float h = 0.5f * x;
    float t;
    asm("tanh.approx.f32 %0, %1;" : "=f"(t) : "f"(h));
    return fmaf(h, t, h);
}
// pack two fp32 -> fp16x2: lower half = even-k val, upper half = odd-k val
__device__ __forceinline__ uint32_t cvt2h(float odd_k, float even_k) {
    uint32_t r; asm("cvt.rn.f16x2.f32 %0, %1, %2;" : "=r"(r) : "f"(odd_k), "f"(even_k)); return r;
}
__device__ __forceinline__ void mma16816h(float* d, uint32_t a0, uint32_t a1,
                                          uint32_t a2, uint32_t a3,
                                          uint32_t b0, uint32_t b1) {
    asm volatile("mma.sync.aligned.m16n8k16.row.col.f32.f16.f16.f32 "
                 "{%0,%1,%2,%3}, {%4,%5,%6,%7}, {%8,%9}, {%0,%1,%2,%3};"
                 : "+f"(d[0]), "+f"(d[1]), "+f"(d[2]), "+f"(d[3])
                 : "r"(a0), "r"(a1), "r"(a2), "r"(a3), "r"(b0), "r"(b1));
}
__device__ __forceinline__ void mbar_init(uint32_t addr, uint32_t cnt) {
    asm volatile("mbarrier.init.shared.b64 [%0], %1;" :: "r"(addr), "r"(cnt) : "memory");
}
__device__ __forceinline__ void mbar_arrive(uint32_t addr) {
    asm volatile("mbarrier.arrive.release.cta.shared::cta.b64 _, [%0];" :: "r"(addr) : "memory");
}
__device__ __forceinline__ void mbar_wait(uint32_t addr, uint32_t parity) {
    asm volatile("{\n\t"
                 ".reg .pred P1;\n\t"
                 "WAIT_%=:\n\t"
                 "mbarrier.try_wait.parity.acquire.cta.shared::cta.b64 P1, [%0], %1, 0x989680;\n\t"
                 "@P1 bra.uni DONE_%=;\n\t"
                 "bra.uni WAIT_%=;\n\t"
                 "DONE_%=:\n\t"
                 "}"
                 :: "r"(addr), "r"(parity) : "memory");
}

// fragment position helpers (k within 128): kt = k>>4, kr = k&15
// t = (kr&7)>>1, reg = (kr>>3)&1, half = kr&1, comp = reg*2 + half
__host__ __device__ __forceinline__ int frag_comp(int kr) { return (((kr >> 3) & 1) << 1) | (kr & 1); }

// ---------------------------------------------------------------------------
// Kernel A: per-step constants (temb @ W1_temb + b1 in permuted layout) + times tail
// ---------------------------------------------------------------------------
__global__ void prep_kernel(const float* __restrict__ times,
                            const float* __restrict__ freqs,
                            const float* __restrict__ dW1, const float* __restrict__ db1,
                            const float* __restrict__ cW1, const float* __restrict__ cb1,
                            const float* __restrict__ log_diff,
                            float* __restrict__ out)
{
    __shared__ float temb[TEMB];
    int tid = threadIdx.x;  // 128 threads, tid = k
    if (tid < NSTEPS + 1) out[TAIL_OFF + tid] = times[tid];
    int kt = tid >> 4, kr = tid & 15;
    int pidx = kt * 16 + ((kr & 7) >> 1) * 4 + frag_comp(kr);  // permuted position
    float gb = log1pf(__expf(log_diff[0]));  // softplus
    for (int i = 0; i < NSTEPS; i++) {
        float t = times[i];
        __syncthreads();
        if (tid < TEMB / 2) {
            float a = 6.2831853071795864f * t * freqs[tid];
            temb[tid]            = sinf(a);
            temb[tid + TEMB / 2] = cosf(a);
        }
        __syncthreads();
        float ad = db1[tid], ac = cb1[tid];
#pragma unroll 8
        for (int mm = 0; mm < TEMB; mm++) {
            float tv = temb[mm];
            ad += tv * dW1[(ZD + CTX + mm) * HID + tid];
            ac += tv * cW1[(ZD + CTX + mm) * HID + tid];
        }
        g_twd[i * HID + pidx] = ad;
        g_twc[i * HID + pidx] = ac;
        if (tid == 0) {
            float dt = times[i + 1] - t;
            g_dts[i]  = dt;
            g_coef[i] = gb * (1.0f - t) * sqrtf(fmaxf(dt, 1e-12f));
        }
    }
}

// ---------------------------------------------------------------------------
// base = ctx @ W1[2:130] for one group of 8 samples, ctx read from GMEM
// ---------------------------------------------------------------------------
__device__ __forceinline__ void compute_base(float* __restrict__ dst,
                                             const float* __restrict__ ctxg,
                                             const float* __restrict__ W1,
                                             int grp, int l)
{
    float acc[8][4];
#pragma unroll
    for (int s8 = 0; s8 < 8; s8++)
#pragma unroll
        for (int c = 0; c < 4; c++) acc[s8][c] = 0.f;
#pragma unroll 2
    for (int r = 0; r < CTX; r++) {
        float w1v[4];
#pragma unroll
        for (int c = 0; c < 4; c++) w1v[c] = W1[(ZD + r) * HID + l + 32 * c];
#pragma unroll
        for (int s8 = 0; s8 < 8; s8++) {
            float a = __ldg(&ctxg[(long long)(grp * 8 + s8) * HID + r]);
#pragma unroll
            for (int c = 0; c < 4; c++) acc[s8][c] += a * w1v[c];
        }
    }
#pragma unroll
    for (int s8 = 0; s8 < 8; s8++)
#pragma unroll
        for (int c = 0; c < 4; c++)
            dst[(grp * 8 + s8) * HID + l + 32 * c] = acc[s8][c];
}

// ---------------------------------------------------------------------------
// Kernel B: persistent 50-step SDE, fp16 tensor-core layer-2, SPB=128.
// ONE 512-thread CTA/SM: 16 warps (8 per MLP), 16 samples/warp, full N=128.
// B-fragments + tables shared by all 8 warps of an MLP (no duplication).
// Two-pass N loop (A-frags precomputed) to fit the 128-reg/thread budget.
// Step sync: pairwise mbarrier handshake, no CTA barrier in the loop.
// SMEM: BfD(32K) BfC(32K) baseRD(64K) baseRC(64K) + tables + psum ≈ 210KB.
// ---------------------------------------------------------------------------
__global__ void __launch_bounds__(NTHREADS, 1)
sde_kernel(const float* __restrict__ z0,
           const float* __restrict__ pctx, const float* __restrict__ cctx,
           const float* __restrict__ noise,
           const float* __restrict__ dW1, const float* __restrict__ dW2,
           const float* __restrict__ db2, const float* __restrict__ dW3,
           const float* __restrict__ db3,
           const float* __restrict__ cW1, const float* __restrict__ cW2,
           const float* __restrict__ cb2, const float* __restrict__ cW3,
           const float* __restrict__ cb3,
           float* __restrict__ out)
{
    extern __shared__ float sm[];
    uint4* BfD    = (uint4*)sm;              // 8kt*8ntp*32lane uint4 = 32KB
    uint4* BfC    = BfD + 2048;              // 32KB
    float* baseRD = (float*)(BfC + 2048);    // 8 wg * 2048 floats = 64KB
    float* baseRC = baseRD + 16384;          // 64KB
    float* wzRs   = baseRC + 16384;          // [mlp][row][kt][t] float4 = 512 f
    float* b2Rs   = wzRs + 512;              // [mlp][ntg][t] float2 = 256 f
    float* W3Rs   = b2Rs + 256;              // [mlp][ntg][t] float4 = 512 f
    float2* psum2 = (float2*)(W3Rs + 512);   // [2 buf][2 mlp][128] float2 = 8KB
    // mbarriers: [2 mlp][8 wg][2 buf] u64 = 256B
    unsigned long long* mbars = (unsigned long long*)(psum2 + 512);

    int tid = threadIdx.x;
    int w = tid >> 5, l = tid & 31;
    int m  = w & 1;        // 0 = diffusion (u), 1 = cnf (f)  [SMSP-aware map]
    int wg = w >> 1;       // sample group of 16 (0..7)
    int t3 = l & 3;        // quad thread
    int g  = l >> 2;       // row 0-7 (sample A); sample B = row g+8
    int blockBase = blockIdx.x * SPB;
    int sA = wg * 16 + g;
    int sB = sA + 8;
    int gsA = blockBase + sA;
    int gsB = blockBase + sB;

    // ================= phase 1 =================
    // 1) base in old [s][k] layout, ctx read directly from gmem
    {
        const float* ctxg = (m ? cctx : pctx) + (long long)blockBase * HID;
        float* dst = m ? baseRC : baseRD;
        compute_base(dst, ctxg, m ? cW1 : dW1, wg * 2,     l);
        compute_base(dst, ctxg, m ? cW1 : dW1, wg * 2 + 1, l);
    }
    __syncthreads();
    // 2) in-place permute base -> fragment order:
    //    ni = ((swg*8 + kt)*32 + lane)*8 + hi8*4 + comp
    {
        float tmpv[32];
#pragma unroll
        for (int a = 0; a < 2; a++) {
            float* arr = a ? baseRC : baseRD;
#pragma unroll
            for (int q = 0; q < 32; q++) tmpv[q] = arr[tid * 32 + q];
            __syncthreads();
#pragma unroll
            for (int q = 0; q < 32; q++) {
                int idx = tid * 32 + q;
                int s = idx >> 7, k = idx & 127;
                int swg = s >> 4, srow = s & 15;
                int hi8 = srow >> 3, gg = srow & 7;
                int kt = k >> 4, kr = k & 15;
                int lane = gg * 4 + ((kr & 7) >> 1);
                int ni = ((swg * 8 + kt) * 32 + lane) * 8 + hi8 * 4 + frag_comp(kr);
                arr[ni] = tmpv[q];
            }
            __syncthreads();
        }
    }
    // 3) W2 -> SINGLE fp16 in B-fragment layout (two ntg per uint4); tables; mbars
    {
        unsigned short* bD16 = (unsigned short*)BfD;
        unsigned short* bC16 = (unsigned short*)BfC;
        for (int e = tid; e < HID * HID; e += NTHREADS) {
            int k = e >> 7, j = e & 127;
            int kt = k >> 4, kr = k & 15;
            int reg = (kr >> 3) & 1, half = kr & 1;
            int lane = (j & 7) * 4 + ((kr & 7) >> 1);
            int ntg = j >> 3;
            int ntp = ntg >> 1, sub = ntg & 1;
            int slot = ((kt * 8 + ntp) * 32 + lane) * 4 + sub * 2 + reg;
            bD16[slot * 2 + half] = __half_as_ushort(__float2half_rn(dW2[e]));
            bC16[slot * 2 + half] = __half_as_ushort(__float2half_rn(cW2[e]));
        }
        // wzR: [mlp][row][kt][t][comp]
        for (int idx = tid; idx < 2 * 2 * HID; idx += NTHREADS) {
            int mlp = idx >> 8, row = (idx >> 7) & 1, k = idx & 127;
            int kt = k >> 4, kr = k & 15;
            float v = (mlp ? cW1 : dW1)[row * HID + k];
            wzRs[((mlp * 2 + row) * 8 + kt) * 16 + ((kr & 7) >> 1) * 4 + frag_comp(kr)] = v;
        }
        // b2R: [mlp][ntg][t][half]   (j = ntg*8 + 2t + half)
        for (int idx = tid; idx < 2 * HID; idx += NTHREADS) {
            int mlp = idx >> 7, j = idx & 127;
            float v = (mlp ? cb2 : db2)[j];
            b2Rs[(mlp * 16 + (j >> 3)) * 8 + ((j & 7) >> 1) * 2 + (j & 1)] = v;
        }
        // W3R: [mlp][ntg][t][(j&1)*2 + d]
        for (int idx = tid; idx < 2 * HID * ZD; idx += NTHREADS) {
            int mlp = idx >> 8, j = (idx >> 1) & 127, d = idx & 1;
            float v = (mlp ? cW3 : dW3)[j * ZD + d];
            W3Rs[(mlp * 16 + (j >> 3)) * 16 + ((j & 7) >> 1) * 4 + (j & 1) * 2 + d] = v;
        }
        // 32 mbarriers, arrive count = 8 (the t3==0 lanes of one warp)
        if (tid < 32)
            mbar_init((uint32_t)__cvta_generic_to_shared(&mbars[tid]), 8);
    }
    __syncthreads();

    // ================= per-warp constant pointers / regs =================
    const uint4*  Bf    = m ? BfC : BfD;
    const float4* bR4   = (const float4*)(m ? baseRC : baseRD);
    const float4* twR4  = (const float4*)(m ? g_twc : g_twd);
    const float4* wz04  = (const float4*)wzRs + (m * 2 + 0) * 32;
    const float4* wz14  = (const float4*)wzRs + (m * 2 + 1) * 32;
    const float2* b2R2  = (const float2*)b2Rs + m * 64;
    const float4* W3R4  = (const float4*)W3Rs + m * 64;
    const float2* noise2 = (const float2*)noise;
    float2* outTraj = (float2*)out;
    float2* outUS   = (float2*)(out + US_OFF);

    // my mbar (arrive) and partner mbar (wait), per buffer
    uint32_t myBar0   = (uint32_t)__cvta_generic_to_shared(&mbars[(m * 8 + wg) * 2 + 0]);
    uint32_t myBar1   = (uint32_t)__cvta_generic_to_shared(&mbars[(m * 8 + wg) * 2 + 1]);
    uint32_t peerBar0 = (uint32_t)__cvta_generic_to_shared(&mbars[((1 - m) * 8 + wg) * 2 + 0]);
    uint32_t peerBar1 = (uint32_t)__cvta_generic_to_shared(&mbars[((1 - m) * 8 + wg) * 2 + 1]);

    float b3_0, b3_1;
    { const float* b3 = m ? cb3 : db3; b3_0 = b3[0]; b3_1 = b3[1]; }

    // init z (all 4 lanes of quad hold both samples' z)
    float2 ziA = __ldg(&((const float2*)z0)[gsA]);
    float2 ziB = __ldg(&((const float2*)z0)[gsB]);
    float zA0 = ziA.x, zA1 = ziA.y, zB0 = ziB.x, zB1 = ziB.y;
    if (m == 1 && t3 == 0) { outTraj[gsA] = ziA; outTraj[gsB] = ziB; }

    // ================= 50-step loop (no CTA barrier inside) =================
    for (int i = 0; i < NSTEPS; i++) {
        float dt = g_dts[i], cf = g_coef[i];
        long long io = (long long)i * N_SAMP;
        float2 xiA = __ldg(&noise2[io + gsA]);
        float2 xiB = __ldg(&noise2[io + gsB]);

        // ---- layer 1: A fragments for all 8 k-tiles (fp16, in regs) ----
        uint32_t Af[8][4];
#pragma unroll
        for (int kt = 0; kt < 8; kt++) {
            float4 bsA = bR4[((wg * 8 + kt) * 32 + l) * 2 + 0];
            float4 bsB = bR4[((wg * 8 + kt) * 32 + l) * 2 + 1];
            float4 tw  = __ldg(&twR4[i * 32 + kt * 4 + t3]);
            float4 w0  = wz04[kt * 4 + t3];
            float4 w1  = wz14[kt * 4 + t3];
            float hAx = fsilu(bsA.x + tw.x + zA0 * w0.x + zA1 * w1.x);
            float hAy = fsilu(bsA.y + tw.y + zA0 * w0.y + zA1 * w1.y);
            float hAz = fsilu(bsA.z + tw.z + zA0 * w0.z + zA1 * w1.z);
            float hAw = fsilu(bsA.w + tw.w + zA0 * w0.w + zA1 * w1.w);
            float hBx = fsilu(bsB.x + tw.x + zB0 * w0.x + zB1 * w1.x);
            float hBy = fsilu(bsB.y + tw.y + zB0 * w0.y + zB1 * w1.y);
            float hBz = fsilu(bsB.z + tw.z + zB0 * w0.z + zB1 * w1.z);
            float hBw = fsilu(bsB.w + tw.w + zB0 * w0.w + zB1 * w1.w);
            Af[kt][0] = cvt2h(hAy, hAx);
            Af[kt][1] = cvt2h(hBy, hBx);
            Af[kt][2] = cvt2h(hAw, hAz);
            Af[kt][3] = cvt2h(hBw, hBz);
        }

        // ---- layer 2 + epilogue in two N passes (8 n-tiles each) ----
        float aA0 = 0.f, aA1 = 0.f, aB0 = 0.f, aB1 = 0.f;
#pragma unroll
        for (int np = 0; np < 2; np++) {
            float d[8][4];
#pragma unroll
            for (int nt = 0; nt < 8; nt++)
#pragma unroll
                for (int c = 0; c < 4; c++) d[nt][c] = 0.f;
#pragma unroll
            for (int kt = 0; kt < 8; kt++) {
                uint4 Bv[4];
#pragma unroll
                for (int q = 0; q < 4; q++)
                    Bv[q] = Bf[(kt * 8 + np * 4 + q) * 32 + l];
#pragma unroll
                for (int q = 0; q < 4; q++) {
                    mma16816h(d[q * 2 + 0], Af[kt][0], Af[kt][1], Af[kt][2], Af[kt][3], Bv[q].x, Bv[q].y);
                    mma16816h(d[q * 2 + 1], Af[kt][0], Af[kt][1], Af[kt][2], Af[kt][3], Bv[q].z, Bv[q].w);
                }
            }
            // epilogue for this pass
#pragma unroll
            for (int nt = 0; nt < 8; nt++) {
                int ntg = np * 8 + nt;
                float2 b2v = b2R2[ntg * 4 + t3];
                float4 w3v = W3R4[ntg * 4 + t3];
                float x0 = fsilu(d[nt][0] + b2v.x);
                float x1 = fsilu(d[nt][1] + b2v.y);
                float x2 = fsilu(d[nt][2] + b2v.x);
                float x3 = fsilu(d[nt][3] + b2v.y);
                aA0 += x0 * w3v.x + x1 * w3v.z;
                aA1 += x0 * w3v.y + x1 * w3v.w;
                aB0 += x2 * w3v.x + x3 * w3v.z;
                aB1 += x2 * w3v.y + x3 * w3v.w;
            }
        }

        // ---- quad reduction (all lanes get sums) ----
        aA0 += __shfl_xor_sync(0xffffffffu, aA0, 1);
        aA1 += __shfl_xor_sync(0xffffffffu, aA1, 1);
        aB0 += __shfl_xor_sync(0xffffffffu, aB0, 1);
        aB1 += __shfl_xor_sync(0xffffffffu, aB1, 1);
        aA0 += __shfl_xor_sync(0xffffffffu, aA0, 2);
        aA1 += __shfl_xor_sync(0xffffffffu, aA1, 2);
        aB0 += __shfl_xor_sync(0xffffffffu, aB0, 2);
        aB1 += __shfl_xor_sync(0xffffffffu, aB1, 2);
        float vA0 = aA0 + b3_0, vA1 = aA1 + b3_1;
        float vB0 = aB0 + b3_0, vB1 = aB1 + b3_1;

        // ---- pairwise mbarrier exchange (double-buffered) ----
        int buf = i & 1;
        uint32_t par = (i >> 1) & 1;
        int bufo = buf * 256;
        if (t3 == 0) {
            psum2[bufo + m * 128 + sA] = make_float2(vA0, vA1);
            psum2[bufo + m * 128 + sB] = make_float2(vB0, vB1);
            mbar_arrive(buf ? myBar1 : myBar0);
        }
        mbar_wait(buf ? peerBar1 : peerBar0, par);
        float2 ovA = psum2[bufo + (1 - m) * 128 + sA];
        float2 ovB = psum2[bufo + (1 - m) * 128 + sB];

        zA0 += (vA0 + ovA.x) * dt + xiA.x * cf;
        zA1 += (vA1 + ovA.y) * dt + xiA.y * cf;
        zB0 += (vB0 + ovB.x) * dt + xiB.x * cf;
        zB1 += (vB1 + ovB.y) * dt + xiB.y * cf;
        if (t3 == 0) {
            if (m == 0) {
                outUS[io + gsA] = make_float2(vA0, vA1);
                outUS[io + gsB] = make_float2(vB0, vB1);
            } else {
                outTraj[(long long)(i + 1) * N_SAMP + gsA] = make_float2(zA0, zA1);
                outTraj[(long long)(i + 1) * N_SAMP + gsB] = make_float2(zB0, zB1);
            }
        }
    }
}

// ---------------------------------------------------------------------------
extern "C" void kernel_launch(void* const* d_in, const int* in_sizes, int n_in,
                              void* d_out, int out_size)
{
    const float* z0       = (const float*)d_in[0];
    const float* pctx     = (const float*)d_in[1];
    const float* cctx     = (const float*)d_in[2];
    const float* times    = (const float*)d_in[3];
    const float* noise    = (const float*)d_in[4];
    const float* freqs    = (const float*)d_in[5];
    const float* dW1      = (const float*)d_in[6];
    const float* db1      = (const float*)d_in[7];
    const float* dW2      = (const float*)d_in[8];
    const float* db2      = (const float*)d_in[9];
    const float* dW3      = (const float*)d_in[10];
    const float* db3      = (const float*)d_in[11];
    const float* cW1      = (const float*)d_in[12];
    const float* cb1      = (const float*)d_in[13];
    const float* cW2      = (const float*)d_in[14];
    const float* cb2      = (const float*)d_in[15];
    const float* cW3      = (const float*)d_in[16];
    const float* cb3      = (const float*)d_in[17];
    const float* log_diff = (const float*)d_in[18];
    float* out = (float*)d_out;

    // Bf 2*32KB + baseR 2*64KB + wzR 2KB + b2R 1KB + W3R 2KB + psum 8KB + mbars 256B
    const int smemB = 2 * 32768 + 2 * 65536 + 512 * 4 + 256 * 4 + 512 * 4 + 512 * 8 + 256;
    cudaFuncSetAttribute(sde_kernel, cudaFuncAttributeMaxDynamicSharedMemorySize, smemB);

    prep_kernel<<<1, 128>>>(times, freqs, dW1, db1, cW1, cb1, log_diff, out);
    sde_kernel<<<N_SAMP / SPB, NTHREADS, smemB>>>(z0, pctx, cctx, noise,
                                                  dW1, dW2, db2, dW3, db3,
                                                  cW1, cW2, cb2, cW3, cb3, out);
}

// round 14
// speedup vs baseline: 1.9876x; 1.0143x over previous
#include <cuda_runtime.h>
#include <cuda_bf16.h>
#include <cuda_fp16.h>
#include <cstdint>

#define N_SAMP   262144
#define ZD       2
#define CTX      128
#define HID      128
#define TEMB     32
#define NSTEPS   50
#define SPB      128     // samples per block
#define NTHREADS 512     // 16 warps: 8 diffusion + 8 cnf, 16 samples each

// output layout: traj [51,N,2] | us [50,N,2] | times [51]
#define US_OFF    ((long long)(NSTEPS+1) * N_SAMP * ZD)
#define TAIL_OFF  (US_OFF + (long long)NSTEPS * N_SAMP * ZD)

// per-step tw constants (PRE-HALVED fp32), permuted into per-lane fragment order:
// idx = i*128 + kt*16 + t*4 + comp,  comp = reg*2 + half  (k = kt*16 + 2t + reg*8 + half)
__device__ float g_twd[NSTEPS * HID];
__device__ float g_twc[NSTEPS * HID];
__device__ float g_dts[NSTEPS];
__device__ float g_coef[NSTEPS];

__device__ __forceinline__ __half2 u2h2(uint32_t u) { return *reinterpret_cast<__half2*>(&u); }

// pack two fp32 -> fp16x2: lower half = 'even', upper = 'odd'
__device__ __forceinline__ uint32_t cvt2h(float odd_k, float even_k) {
    uint32_t r; asm("cvt.rn.f16x2.f32 %0, %1, %2;" : "=r"(r) : "f"(odd_k), "f"(even_k)); return r;
}
__device__ __forceinline__ uint32_t tanh2u(uint32_t x) {
    uint32_t r; asm("tanh.approx.f16x2 %0, %1;" : "=r"(r) : "r"(x)); return r;
}
__device__ __forceinline__ void mma16816h(float* d, uint32_t a0, uint32_t a1,
                                          uint32_t a2, uint32_t a3,
                                          uint32_t b0, uint32_t b1) {
    asm volatile("mma.sync.aligned.m16n8k16.row.col.f32.f16.f16.f32 "
                 "{%0,%1,%2,%3}, {%4,%5,%6,%7}, {%8,%9}, {%0,%1,%2,%3};"
                 : "+f"(d[0]), "+f"(d[1]), "+f"(d[2]), "+f"(d[3])
                 : "r"(a0), "r"(a1), "r"(a2), "r"(a3), "r"(b0), "r"(b1));
}
__device__ __forceinline__ void mbar_init(uint32_t addr, uint32_t cnt) {
    asm volatile("mbarrier.init.shared.b64 [%0], %1;" :: "r"(addr), "r"(cnt) : "memory");
}
__device__ __forceinline__ void mbar_arrive(uint32_t addr) {
    asm volatile("mbarrier.arrive.release.cta.shared::cta.b64 _, [%0];" :: "r"(addr) : "memory");
}
__device__ __forceinline__ void mbar_wait(uint32_t addr, uint32_t parity) {
    asm volatile("{\n\t"
                 ".reg .pred P1;\n\t"
                 "WAIT_%=:\n\t"
                 "mbarrier.try_wait.parity.acquire.cta.shared::cta.b64 P1, [%0], %1, 0x989680;\n\t"
                 "@P1 bra.uni DONE_%=;\n\t"
                 "bra.uni WAIT_%=;\n\t"
                 "DONE_%=:\n\t"
                 "}"
                 :: "r"(addr), "r"(parity) : "memory");
}

// fragment position helpers (k within 128): kt = k>>4, kr = k&15
// t = (kr&7)>>1, reg = (kr>>3)&1, half = kr&1, comp = reg*2 + half
__host__ __device__ __forceinline__ int frag_comp(int kr) { return (((kr >> 3) & 1) << 1) | (kr & 1); }

// ---------------------------------------------------------------------------
// Kernel A: per-step constants (PRE-HALVED tw, permuted) + times tail
// ---------------------------------------------------------------------------
__global__ void prep_kernel(const float* __restrict__ times,
                            const float* __restrict__ freqs,
                            const float* __restrict__ dW1, const float* __restrict__ db1,
                            const float* __restrict__ cW1, const float* __restrict__ cb1,
                            const float* __restrict__ log_diff,
                            float* __restrict__ out)
{
    __shared__ float temb[TEMB];
    int tid = threadIdx.x;  // 128 threads, tid = k
    if (tid < NSTEPS + 1) out[TAIL_OFF + tid] = times[tid];
    int kt = tid >> 4, kr = tid & 15;
    int pidx = kt * 16 + ((kr & 7) >> 1) * 4 + frag_comp(kr);  // permuted position
    float gb = log1pf(__expf(log_diff[0]));  // softplus
    for (int i = 0; i < NSTEPS; i++) {
        float t = times[i];
        __syncthreads();
        if (tid < TEMB / 2) {
            float a = 6.2831853071795864f * t * freqs[tid];
            temb[tid]            = sinf(a);
            temb[tid + TEMB / 2] = cosf(a);
        }
        __syncthreads();
        float ad = db1[tid], ac = cb1[tid];
#pragma unroll 8
        for (int mm = 0; mm < TEMB; mm++) {
            float tv = temb[mm];
            ad += tv * dW1[(ZD + CTX + mm) * HID + tid];
            ac += tv * cW1[(ZD + CTX + mm) * HID + tid];
        }
        g_twd[i * HID + pidx] = 0.5f * ad;   // pre-halved (fp32, exact rescale)
        g_twc[i * HID + pidx] = 0.5f * ac;
        if (tid == 0) {
            float dt = times[i + 1] - t;
            g_dts[i]  = dt;
            g_coef[i] = gb * (1.0f - t) * sqrtf(fmaxf(dt, 1e-12f));
        }
    }
}

// ---------------------------------------------------------------------------
// base = ctx @ W1[2:130] for one group of 8 samples, ctx read from GMEM (fp32)
// ---------------------------------------------------------------------------
__device__ __forceinline__ void compute_base(float* __restrict__ dst,
                                             const float* __restrict__ ctxg,
                                             const float* __restrict__ W1,
                                             int grp, int l)
{
    float acc[8][4];
#pragma unroll
    for (int s8 = 0; s8 < 8; s8++)
#pragma unroll
        for (int c = 0; c < 4; c++) acc[s8][c] = 0.f;
#pragma unroll 2
    for (int r = 0; r < CTX; r++) {
        float w1v[4];
#pragma unroll
        for (int c = 0; c < 4; c++) w1v[c] = W1[(ZD + r) * HID + l + 32 * c];
#pragma unroll
        for (int s8 = 0; s8 < 8; s8++) {
            float a = __ldg(&ctxg[(long long)(grp * 8 + s8) * HID + r]);
#pragma unroll
            for (int c = 0; c < 4; c++) acc[s8][c] += a * w1v[c];
        }
    }
#pragma unroll
    for (int s8 = 0; s8 < 8; s8++)
#pragma unroll
        for (int c = 0; c < 4; c++)
            dst[(grp * 8 + s8) * HID + l + 32 * c] = acc[s8][c];
}

// ---------------------------------------------------------------------------
// Kernel B: persistent 50-step SDE, fp16 tensor-core layer-2, SPB=128.
// Exactly the R12 structure (fp32 layer-1 arithmetic, fp16 only at the MMA
// interface) with ONE change: silu's tanh evaluated via tanh.approx.f16x2
// (arg/result fp16, h and multiply fp32) -> MUFU per warp-step halves.
// base/tw/wz/b2 are PRE-HALVED in fp32 so layer-1 produces h2 = x/2 directly.
// Step sync: pairwise mbarrier handshake, no CTA barrier in the loop.
// SMEM: BfD(32K) BfC(32K) baseRD(64K) baseRC(64K) + tables + psum ~ 206KB.
// ---------------------------------------------------------------------------
__global__ void __launch_bounds__(NTHREADS, 1)
sde_kernel(const float* __restrict__ z0,
           const float* __restrict__ pctx, const float* __restrict__ cctx,
           const float* __restrict__ noise,
           const float* __restrict__ dW1, const float* __restrict__ dW2,
           const float* __restrict__ db2, const float* __restrict__ dW3,
           const float* __restrict__ db3,
           const float* __restrict__ cW1, const float* __restrict__ cW2,
           const float* __restrict__ cb2, const float* __restrict__ cW3,
           const float* __restrict__ cb3,
           float* __restrict__ out)
{
    extern __shared__ float sm[];
    uint4* BfD    = (uint4*)sm;              // 8kt*8ntp*32lane uint4 = 32KB
    uint4* BfC    = BfD + 2048;              // 32KB
    float* baseRD = (float*)(BfC + 2048);    // 8 wg * 2048 floats = 64KB (pre-halved)
    float* baseRC = baseRD + 16384;          // 64KB
    float* wzRs   = baseRC + 16384;          // [mlp][row][kt][t] float4 = 512 f (pre-halved)
    float* b2Rs   = wzRs + 512;              // [mlp][ntg][t] float2 = 256 f (pre-halved)
    float* W3Rs   = b2Rs + 256;              // [mlp][ntg][t] float4 = 512 f
    float2* psum2 = (float2*)(W3Rs + 512);   // [2 buf][2 mlp][128] float2 = 8KB
    // mbarriers: [2 mlp][8 wg][2 buf] u64 = 256B
    unsigned long long* mbars = (unsigned long long*)(psum2 + 512);

    int tid = threadIdx.x;
    int w = tid >> 5, l = tid & 31;
    int m  = w & 1;        // 0 = diffusion (u), 1 = cnf (f)  [SMSP-aware map]
    int wg = w >> 1;       // sample group of 16 (0..7)
    int t3 = l & 3;        // quad thread
    int g  = l >> 2;       // row 0-7 (sample A); sample B = row g+8
    int blockBase = blockIdx.x * SPB;
    int sA = wg * 16 + g;
    int sB = sA + 8;
    int gsA = blockBase + sA;
    int gsB = blockBase + sB;

    // ================= phase 1 =================
    // 1) base in old [s][k] layout, ctx read directly from gmem
    {
        const float* ctxg = (m ? cctx : pctx) + (long long)blockBase * HID;
        float* dst = m ? baseRC : baseRD;
        compute_base(dst, ctxg, m ? cW1 : dW1, wg * 2,     l);
        compute_base(dst, ctxg, m ? cW1 : dW1, wg * 2 + 1, l);
    }
    __syncthreads();
    // 2) in-place permute base -> fragment order, PRE-HALVED (fp32):
    //    ni = ((swg*8 + kt)*32 + lane)*8 + hi8*4 + comp
    {
        float tmpv[32];
#pragma unroll
        for (int a = 0; a < 2; a++) {
            float* arr = a ? baseRC : baseRD;
#pragma unroll
            for (int q = 0; q < 32; q++) tmpv[q] = arr[tid * 32 + q];
            __syncthreads();
#pragma unroll
            for (int q = 0; q < 32; q++) {
                int idx = tid * 32 + q;
                int s = idx >> 7, k = idx & 127;
                int swg = s >> 4, srow = s & 15;
                int hi8 = srow >> 3, gg = srow & 7;
                int kt = k >> 4, kr = k & 15;
                int lane = gg * 4 + ((kr & 7) >> 1);
                int ni = ((swg * 8 + kt) * 32 + lane) * 8 + hi8 * 4 + frag_comp(kr);
                arr[ni] = 0.5f * tmpv[q];
            }
            __syncthreads();
        }
    }
    // 3) W2 -> SINGLE fp16 in B-fragment layout (two ntg per uint4); tables; mbars
    {
        unsigned short* bD16 = (unsigned short*)BfD;
        unsigned short* bC16 = (unsigned short*)BfC;
        for (int e = tid; e < HID * HID; e += NTHREADS) {
            int k = e >> 7, j = e & 127;
            int kt = k >> 4, kr = k & 15;
            int reg = (kr >> 3) & 1, half = kr & 1;
            int lane = (j & 7) * 4 + ((kr & 7) >> 1);
            int ntg = j >> 3;
            int ntp = ntg >> 1, sub = ntg & 1;
            int slot = ((kt * 8 + ntp) * 32 + lane) * 4 + sub * 2 + reg;
            bD16[slot * 2 + half] = __half_as_ushort(__float2half_rn(dW2[e]));
            bC16[slot * 2 + half] = __half_as_ushort(__float2half_rn(cW2[e]));
        }
        // wzR (PRE-HALVED): [mlp][row][kt][t][comp]
        for (int idx = tid; idx < 2 * 2 * HID; idx += NTHREADS) {
            int mlp = idx >> 8, row = (idx >> 7) & 1, k = idx & 127;
            int kt = k >> 4, kr = k & 15;
            float v = 0.5f * (mlp ? cW1 : dW1)[row * HID + k];
            wzRs[((mlp * 2 + row) * 8 + kt) * 16 + ((kr & 7) >> 1) * 4 + frag_comp(kr)] = v;
        }
        // b2R (PRE-HALVED): [mlp][ntg][t][half]   (j = ntg*8 + 2t + half)
        for (int idx = tid; idx < 2 * HID; idx += NTHREADS) {
            int mlp = idx >> 7, j = idx & 127;
            float v = 0.5f * (mlp ? cb2 : db2)[j];
            b2Rs[(mlp * 16 + (j >> 3)) * 8 + ((j & 7) >> 1) * 2 + (j & 1)] = v;
        }
        // W3R: [mlp][ntg][t][(j&1)*2 + d]
        for (int idx = tid; idx < 2 * HID * ZD; idx += NTHREADS) {
            int mlp = idx >> 8, j = (idx >> 1) & 127, d = idx & 1;
            float v = (mlp ? cW3 : dW3)[j * ZD + d];
            W3Rs[(mlp * 16 + (j >> 3)) * 16 + ((j & 7) >> 1) * 4 + (j & 1) * 2 + d] = v;
        }
        // 32 mbarriers, arrive count = 8 (the t3==0 lanes of one warp)
        if (tid < 32)
            mbar_init((uint32_t)__cvta_generic_to_shared(&mbars[tid]), 8);
    }
    __syncthreads();

    // ================= per-warp constant pointers / regs =================
    const uint4*  Bf    = m ? BfC : BfD;
    const float4* bR4   = (const float4*)(m ? baseRC : baseRD);
    const float4* twR4  = (const float4*)(m ? g_twc : g_twd);
    const float4* wz04  = (const float4*)wzRs + (m * 2 + 0) * 32;
    const float4* wz14  = (const float4*)wzRs + (m * 2 + 1) * 32;
    const float2* b2R2  = (const float2*)b2Rs + m * 64;
    const float4* W3R4  = (const float4*)W3Rs + m * 64;
    const float2* noise2 = (const float2*)noise;
    float2* outTraj = (float2*)out;
    float2* outUS   = (float2*)(out + US_OFF);

    uint32_t myBar0   = (uint32_t)__cvta_generic_to_shared(&mbars[(m * 8 + wg) * 2 + 0]);
    uint32_t myBar1   = (uint32_t)__cvta_generic_to_shared(&mbars[(m * 8 + wg) * 2 + 1]);
    uint32_t peerBar0 = (uint32_t)__cvta_generic_to_shared(&mbars[((1 - m) * 8 + wg) * 2 + 0]);
    uint32_t peerBar1 = (uint32_t)__cvta_generic_to_shared(&mbars[((1 - m) * 8 + wg) * 2 + 1]);

    float b3_0, b3_1;
    { const float* b3 = m ? cb3 : db3; b3_0 = b3[0]; b3_1 = b3[1]; }

    // init z (all 4 lanes of quad hold both samples' z)
    float2 ziA = __ldg(&((const float2*)z0)[gsA]);
    float2 ziB = __ldg(&((const float2*)z0)[gsB]);
    float zA0 = ziA.x, zA1 = ziA.y, zB0 = ziB.x, zB1 = ziB.y;
    if (m == 1 && t3 == 0) { outTraj[gsA] = ziA; outTraj[gsB] = ziB; }

    // ================= 50-step loop (no CTA barrier inside) =================
    for (int i = 0; i < NSTEPS; i++) {
        float dt = g_dts[i], cf = g_coef[i];
        long long io = (long long)i * N_SAMP;
        float2 xiA = __ldg(&noise2[io + gsA]);
        float2 xiB = __ldg(&noise2[io + gsB]);

        // ---- layer 1 (fp32 h2 = x/2; tanh via f16x2; A frags fp16) ----
        uint32_t Af[8][4];
#pragma unroll
        for (int kt = 0; kt < 8; kt++) {
            float4 bsA = bR4[((wg * 8 + kt) * 32 + l) * 2 + 0];  // pre-halved
            float4 bsB = bR4[((wg * 8 + kt) * 32 + l) * 2 + 1];
            float4 tw  = __ldg(&twR4[i * 32 + kt * 4 + t3]);     // pre-halved
            float4 w0  = wz04[kt * 4 + t3];                      // pre-halved
            float4 w1  = wz14[kt * 4 + t3];
            float hAx = bsA.x + tw.x + zA0 * w0.x + zA1 * w1.x;  // = x/2
            float hAy = bsA.y + tw.y + zA0 * w0.y + zA1 * w1.y;
            float hAz = bsA.z + tw.z + zA0 * w0.z + zA1 * w1.z;
            float hAw = bsA.w + tw.w + zA0 * w0.w + zA1 * w1.w;
            float hBx = bsB.x + tw.x + zB0 * w0.x + zB1 * w1.x;
            float hBy = bsB.y + tw.y + zB0 * w0.y + zB1 * w1.y;
            float hBz = bsB.z + tw.z + zB0 * w0.z + zB1 * w1.z;
            float hBw = bsB.w + tw.w + zB0 * w0.w + zB1 * w1.w;
            uint32_t tAu01 = tanh2u(cvt2h(hAy, hAx));
            uint32_t tAu23 = tanh2u(cvt2h(hAw, hAz));
            uint32_t tBu01 = tanh2u(cvt2h(hBy, hBx));
            uint32_t tBu23 = tanh2u(cvt2h(hBw, hBz));
            float2 tA01 = __half22float2(u2h2(tAu01));
            float2 tA23 = __half22float2(u2h2(tAu23));
            float2 tB01 = __half22float2(u2h2(tBu01));
            float2 tB23 = __half22float2(u2h2(tBu23));
            // silu(x) = h2*(1+t) = h2 + h2*t   (fp32)
            float xAx = fmaf(hAx, tA01.x, hAx);
            float xAy = fmaf(hAy, tA01.y, hAy);
            float xAz = fmaf(hAz, tA23.x, hAz);
            float xAw = fmaf(hAw, tA23.y, hAw);
            float xBx = fmaf(hBx, tB01.x, hBx);
            float xBy = fmaf(hBy, tB01.y, hBy);
            float xBz = fmaf(hBz, tB23.x, hBz);
            float xBw = fmaf(hBw, tB23.y, hBw);
            Af[kt][0] = cvt2h(xAy, xAx);
            Af[kt][1] = cvt2h(xBy, xBx);
            Af[kt][2] = cvt2h(xAw, xAz);
            Af[kt][3] = cvt2h(xBw, xBz);
        }

        // ---- layer 2 + epilogue in two N passes (8 n-tiles each) ----
        float aA0 = 0.f, aA1 = 0.f, aB0 = 0.f, aB1 = 0.f;
#pragma unroll
        for (int np = 0; np < 2; np++) {
            float d[8][4];
#pragma unroll
            for (int nt = 0; nt < 8; nt++)
#pragma unroll
                for (int c = 0; c < 4; c++) d[nt][c] = 0.f;
#pragma unroll
            for (int kt = 0; kt < 8; kt++) {
                uint4 Bv[4];
#pragma unroll
                for (int q = 0; q < 4; q++)
                    Bv[q] = Bf[(kt * 8 + np * 4 + q) * 32 + l];
#pragma unroll
                for (int q = 0; q < 4; q++) {
                    mma16816h(d[q * 2 + 0], Af[kt][0], Af[kt][1], Af[kt][2], Af[kt][3], Bv[q].x, Bv[q].y);
                    mma16816h(d[q * 2 + 1], Af[kt][0], Af[kt][1], Af[kt][2], Af[kt][3], Bv[q].z, Bv[q].w);
                }
            }
            // epilogue: silu via f16x2 tanh (h fp32, multiply fp32)
#pragma unroll
            for (int nt = 0; nt < 8; nt++) {
                int ntg = np * 8 + nt;
                float2 b2v = b2R2[ntg * 4 + t3];  // pre-halved
                float4 w3v = W3R4[ntg * 4 + t3];
                float hx0 = fmaf(d[nt][0], 0.5f, b2v.x);
                float hx1 = fmaf(d[nt][1], 0.5f, b2v.y);
                float hx2 = fmaf(d[nt][2], 0.5f, b2v.x);
                float hx3 = fmaf(d[nt][3], 0.5f, b2v.y);
                uint32_t thA = tanh2u(cvt2h(hx1, hx0));
                uint32_t thB = tanh2u(cvt2h(hx3, hx2));
                float2 tA = __half22float2(u2h2(thA));
                float2 tB = __half22float2(u2h2(thB));
                float x0 = fmaf(hx0, tA.x, hx0);
                float x1 = fmaf(hx1, tA.y, hx1);
                float x2 = fmaf(hx2, tB.x, hx2);
                float x3 = fmaf(hx3, tB.y, hx3);
                aA0 += x0 * w3v.x + x1 * w3v.z;
                aA1 += x0 * w3v.y + x1 * w3v.w;
                aB0 += x2 * w3v.x + x3 * w3v.z;
                aB1 += x2 * w3v.y + x3 * w3v.w;
            }
        }

        // ---- quad reduction (all lanes get sums) ----
        aA0 += __shfl_xor_sync(0xffffffffu, aA0, 1);
        aA1 += __shfl_xor_sync(0xffffffffu, aA1, 1);
        aB0 += __shfl_xor_sync(0xffffffffu, aB0, 1);
        aB1 += __shfl_xor_sync(0xffffffffu, aB1, 1);
        aA0 += __shfl_xor_sync(0xffffffffu, aA0, 2);
        aA1 += __shfl_xor_sync(0xffffffffu, aA1, 2);
        aB0 += __shfl_xor_sync(0xffffffffu, aB0, 2);
        aB1 += __shfl_xor_sync(0xffffffffu, aB1, 2);
        float vA0 = aA0 + b3_0, vA1 = aA1 + b3_1;
        float vB0 = aB0 + b3_0, vB1 = aB1 + b3_1;

        // ---- pairwise mbarrier exchange (double-buffered) ----
        int buf = i & 1;
        uint32_t par = (i >> 1) & 1;
        int bufo = buf * 256;
        if (t3 == 0) {
            psum2[bufo + m * 128 + sA] = make_float2(vA0, vA1);
            psum2[bufo + m * 128 + sB] = make_float2(vB0, vB1);
            mbar_arrive(buf ? myBar1 : myBar0);
        }
        mbar_wait(buf ? peerBar1 : peerBar0, par);
        float2 ovA = psum2[bufo + (1 - m) * 128 + sA];
        float2 ovB = psum2[bufo + (1 - m) * 128 + sB];

        zA0 += (vA0 + ovA.x) * dt + xiA.x * cf;
        zA1 += (vA1 + ovA.y) * dt + xiA.y * cf;
        zB0 += (vB0 + ovB.x) * dt + xiB.x * cf;
        zB1 += (vB1 + ovB.y) * dt + xiB.y * cf;
        if (t3 == 0) {
            if (m == 0) {
                outUS[io + gsA] = make_float2(vA0, vA1);
                outUS[io + gsB] = make_float2(vB0, vB1);
            } else {
                outTraj[(long long)(i + 1) * N_SAMP + gsA] = make_float2(zA0, zA1);
                outTraj[(long long)(i + 1) * N_SAMP + gsB] = make_float2(zB0, zB1);
            }
        }
    }
}

// ---------------------------------------------------------------------------
extern "C" void kernel_launch(void* const* d_in, const int* in_sizes, int n_in,
                              void* d_out, int out_size)
{
    const float* z0       = (const float*)d_in[0];
    const float* pctx     = (const float*)d_in[1];
    const float* cctx     = (const float*)d_in[2];
    const float* times    = (const float*)d_in[3];
    const float* noise    = (const float*)d_in[4];
    const float* freqs    = (const float*)d_in[5];
    const float* dW1      = (const float*)d_in[6];
    const float* db1      = (const float*)d_in[7];
    const float* dW2      = (const float*)d_in[8];
    const float* db2      = (const float*)d_in[9];
    const float* dW3      = (const float*)d_in[10];
    const float* db3      = (const float*)d_in[11];
    const float* cW1      = (const float*)d_in[12];
    const float* cb1      = (const float*)d_in[13];
    const float* cW2      = (const float*)d_in[14];
    const float* cb2      = (const float*)d_in[15];
    const float* cW3      = (const float*)d_in[16];
    const float* cb3      = (const float*)d_in[17];
    const float* log_diff = (const float*)d_in[18];
    float* out = (float*)d_out;

    // Bf 2*32KB + baseR 2*64KB + wzR 2KB + b2R 1KB + W3R 2KB + psum 8KB + mbars 256B
    const int smemB = 2 * 32768 + 2 * 65536 + 512 * 4 + 256 * 4 + 512 * 4 + 512 * 8 + 256;
    cudaFuncSetAttribute(sde_kernel, cudaFuncAttributeMaxDynamicSharedMemorySize, smemB);

    prep_kernel<<<1, 128>>>(times, freqs, dW1, db1, cW1, cb1, log_diff, out);
    sde_kernel<<<N_SAMP / SPB, NTHREADS, smemB>>>(z0, pctx, cctx, noise,
                                                  dW1, dW2, db2, dW3, db3,
                                                  cW1, cW2, cb2, cW3, cb3, out);
}